// round 3
// baseline (speedup 1.0000x reference)
#include <cuda_runtime.h>
#include <cstddef>

// Problem shapes (fixed for this problem instance)
#define BB   32
#define TT   8192
#define QD   512
#define VD   256
#define DD   128

#define TILE_T 128   // t-rows per score block
#define KC     16    // K chunk for score GEMM

// ---------------- device scratch (no allocation allowed) ----------------
__device__ float g_q[BB * DD];                 // projected query + bq
__device__ float g_score[BB * TT];             // raw additive scores (incl. bias)
__device__ float g_Spart[32][BB][VD];          // partial alignment@value per t-chunk
__device__ float g_S[BB * VD];                 // reduced alignment@value
__device__ float g_sumA[BB];                   // per-batch sum of alignment

// ---------------- f32x2 packed-FMA helpers (sm_100+) ----------------
__device__ __forceinline__ unsigned long long pack2(float lo, float hi) {
    unsigned long long r;
    asm("mov.b64 %0, {%1, %2};" : "=l"(r) : "f"(lo), "f"(hi));
    return r;
}
__device__ __forceinline__ void unpack2(unsigned long long v, float& lo, float& hi) {
    asm("mov.b64 {%0, %1}, %2;" : "=f"(lo), "=f"(hi) : "l"(v));
}
__device__ __forceinline__ void ffma2(unsigned long long& d,
                                      unsigned long long a,
                                      unsigned long long b) {
    asm("fma.rn.f32x2 %0, %1, %2, %0;" : "+l"(d) : "l"(a), "l"(b));
}

// ---------------- kernel A: q = query @ Wq + bq ----------------
__global__ void qproj_kernel(const float* __restrict__ query,
                             const float* __restrict__ Wq,
                             const float* __restrict__ bq) {
    int b = blockIdx.x;
    int d = threadIdx.x;           // 128 threads
    float acc = bq[d];
    const float* qr = query + (size_t)b * QD;
#pragma unroll 8
    for (int k = 0; k < QD; k++)
        acc += qr[k] * Wq[(size_t)k * DD + d];
    g_q[b * DD + d] = acc;
}

// ---------------- kernel B: fused v-GEMM + Bahdanau score ----------------
// score[b,t] = sum_d av[d] * tanh(q[b,d] + bv[d] + (value[b,t,:] @ Wv)[d]) + bias
__global__ __launch_bounds__(256) void score_kernel(
    const float* __restrict__ value,
    const float* __restrict__ Wv,
    const float* __restrict__ bv,
    const float* __restrict__ av,
    const float* __restrict__ sbias) {

    __shared__ __align__(16) float bsh[KC][DD];        // Wv chunk [k][d]
    __shared__ float vsh[KC][TILE_T + 1];              // value chunk, k-major [k][t]

    int b  = blockIdx.y;
    int t0 = blockIdx.x * TILE_T;
    int tid = threadIdx.x;
    int tx = tid & 15;             // 16 column groups (8 d-cols each)
    int ty = tid >> 4;             // 16 row groups   (8 t-rows each)

    unsigned long long acc[8][4];  // [row i][col pair j] packed fp32 pairs
#pragma unroll
    for (int i = 0; i < 8; i++)
#pragma unroll
        for (int j = 0; j < 4; j++) acc[i][j] = 0ull;

    const float* vptr = value + ((size_t)b * TT + t0) * VD;

    for (int kc = 0; kc < VD; kc += KC) {
        // load value tile 128t x 16k (transposed into smem)
#pragma unroll
        for (int r = 0; r < 2; r++) {
            int idx = tid + r * 256;             // 0..511 float4s
            int row = idx >> 2;
            int k4  = (idx & 3) * 4;
            float4 vv = *(const float4*)(vptr + (size_t)row * VD + kc + k4);
            vsh[k4 + 0][row] = vv.x;
            vsh[k4 + 1][row] = vv.y;
            vsh[k4 + 2][row] = vv.z;
            vsh[k4 + 3][row] = vv.w;
        }
        // load Wv chunk 16k x 128d
#pragma unroll
        for (int r = 0; r < 2; r++) {
            int idx = tid + r * 256;             // 0..511 float4s
            int kk  = idx >> 5;
            int d4  = (idx & 31) * 4;
            *(float4*)&bsh[kk][d4] = *(const float4*)(Wv + (size_t)(kc + kk) * DD + d4);
        }
        __syncthreads();

#pragma unroll
        for (int kk = 0; kk < KC; kk++) {
            unsigned long long ap[8];
#pragma unroll
            for (int i = 0; i < 8; i++) {
                float a = vsh[kk][ty * 8 + i];
                ap[i] = pack2(a, a);
            }
            unsigned long long bp[4];
#pragma unroll
            for (int j = 0; j < 4; j++)
                bp[j] = *(const unsigned long long*)&bsh[kk][tx * 8 + j * 2];
#pragma unroll
            for (int i = 0; i < 8; i++)
#pragma unroll
                for (int j = 0; j < 4; j++)
                    ffma2(acc[i][j], ap[i], bp[j]);
        }
        __syncthreads();
    }

    // epilogue: tanh + dot with attention_v, reduce across the 16 tx lanes
    float qv[8], avv[8];
#pragma unroll
    for (int j = 0; j < 8; j++) {
        int c = tx * 8 + j;
        qv[j]  = g_q[b * DD + c] + bv[c];
        avv[j] = av[c];
    }
    float part[8];
#pragma unroll
    for (int i = 0; i < 8; i++) {
        float s = 0.f;
#pragma unroll
        for (int j = 0; j < 4; j++) {
            float lo, hi;
            unpack2(acc[i][j], lo, hi);
            s += avv[2 * j]     * tanhf(qv[2 * j]     + lo);
            s += avv[2 * j + 1] * tanhf(qv[2 * j + 1] + hi);
        }
        part[i] = s;
    }
#pragma unroll
    for (int o = 8; o >= 1; o >>= 1)
#pragma unroll
        for (int i = 0; i < 8; i++)
            part[i] += __shfl_down_sync(0xffffffffu, part[i], o, 16);

    if (tx == 0) {
        float bias = *sbias;
#pragma unroll
        for (int i = 0; i < 8; i++)
            g_score[b * TT + t0 + ty * 8 + i] = part[i] + bias;
    }
}

// ---------------- kernel C: monotonic-attention scan ----------------
__device__ __forceinline__ float sigmoidf_stable(float s) {
    if (s >= 0.f) { float e = expf(-s); return 1.f / (1.f + e); }
    float e = expf(s); return e / (1.f + e);
}

__device__ float block_exscan256(float v, float* sm) {
    float x = v;
#pragma unroll
    for (int o = 1; o < 32; o <<= 1) {
        float y = __shfl_up_sync(0xffffffffu, x, o);
        if ((threadIdx.x & 31) >= o) x += y;
    }
    int warp = threadIdx.x >> 5;
    __syncthreads();                     // protect sm from previous use
    if ((threadIdx.x & 31) == 31) sm[warp] = x;
    __syncthreads();
    float woff = 0.f;
    for (int w = 0; w < warp; w++) woff += sm[w];
    return woff + x - v;                 // exclusive prefix
}

__global__ __launch_bounds__(256) void scan_kernel(
    const float* __restrict__ prev, float* __restrict__ out_align) {
    __shared__ float sm[8];
    const float TINYF = 1.17549435e-38f;
    int b = blockIdx.x;
    int tid = threadIdx.x;
    const float* sc = g_score + (size_t)b * TT;
    const float* pa = prev + (size_t)b * TT;
    int base = tid * 32;

    // phase 1: chunk sums of l = log(clip(1-p))
    float suml = 0.f;
    for (int c = 0; c < 32; c++) {
        float p  = sigmoidf_stable(sc[base + c]);
        float om = fminf(fmaxf(1.f - p, TINYF), 1.f);
        suml += logf(om);
    }
    float prefl = block_exscan256(suml, sm);

    // phase 2: chunk sums of u = prev / clip(cp)
    float run = 0.f, sumu = 0.f;
    for (int c = 0; c < 32; c++) {
        float p  = sigmoidf_stable(sc[base + c]);
        float om = fminf(fmaxf(1.f - p, TINYF), 1.f);
        float l  = logf(om);
        float cp = expf(prefl + run);    // exclusive cumsum of logs
        run += l;
        float u = pa[base + c] / fminf(fmaxf(cp, 1e-10f), 1.f);
        sumu += u;
    }
    float prefu = block_exscan256(sumu, sm);

    // phase 3: alignment = p * cp * inclusive_cumsum(u)
    run = 0.f;
    float runu = 0.f, suma = 0.f;
    for (int c = 0; c < 32; c++) {
        float p  = sigmoidf_stable(sc[base + c]);
        float om = fminf(fmaxf(1.f - p, TINYF), 1.f);
        float l  = logf(om);
        float cp = expf(prefl + run);
        run += l;
        float u = pa[base + c] / fminf(fmaxf(cp, 1e-10f), 1.f);
        runu += u;
        float al = p * cp * (prefu + runu);
        out_align[(size_t)b * TT + base + c] = al;
        suma += al;
    }
    float prefa = block_exscan256(suma, sm);
    if (tid == 255) g_sumA[b] = prefa + suma;
}

// ---------------- kernel D: partial S = alignment @ value (per t-chunk) ----------------
__global__ __launch_bounds__(256) void ctx_reduce_kernel(
    const float* __restrict__ value, const float* __restrict__ align) {
    __shared__ float ash[256];
    int tc = blockIdx.x;               // 32 t-chunks of 256
    int b  = blockIdx.y;
    int tid = threadIdx.x;
    int t0 = tc * 256;
    ash[tid] = align[(size_t)b * TT + t0 + tid];
    __syncthreads();
    const float* vp = value + ((size_t)b * TT + t0) * VD + tid;
    float acc = 0.f;
#pragma unroll 8
    for (int t = 0; t < 256; t++)
        acc += ash[t] * vp[(size_t)t * VD];
    g_Spart[tc][b][tid] = acc;         // plain store: deterministic
}

// ---------------- kernel E1: reduce partials ----------------
__global__ void ctx_sum_kernel() {
    int b = blockIdx.x;
    int k = threadIdx.x;               // 256
    float s = 0.f;
#pragma unroll
    for (int c = 0; c < 32; c++) s += g_Spart[c][b][k];
    g_S[b * VD + k] = s;
}

// ---------------- kernel E2: context = S @ Wv + sumA * bv ----------------
__global__ void ctx_final_kernel(const float* __restrict__ Wv,
                                 const float* __restrict__ bv,
                                 float* __restrict__ out_ctx) {
    int b = blockIdx.x;
    int d = threadIdx.x;               // 128
    float acc = g_sumA[b] * bv[d];
#pragma unroll 8
    for (int k = 0; k < VD; k++)
        acc += g_S[b * VD + k] * Wv[(size_t)k * DD + d];
    out_ctx[b * DD + d] = acc;
}

// ---------------- launcher ----------------
extern "C" void kernel_launch(void* const* d_in, const int* in_sizes, int n_in,
                              void* d_out, int out_size) {
    (void)in_sizes; (void)n_in; (void)out_size;
    const float* query = (const float*)d_in[0];
    const float* value = (const float*)d_in[1];
    const float* prev  = (const float*)d_in[2];
    const float* Wq    = (const float*)d_in[3];
    const float* bq    = (const float*)d_in[4];
    const float* Wv    = (const float*)d_in[5];
    const float* bv    = (const float*)d_in[6];
    const float* av    = (const float*)d_in[7];
    const float* sbias = (const float*)d_in[8];

    float* out       = (float*)d_out;
    float* out_ctx   = out;                  // [32, 128]
    float* out_align = out + BB * DD;        // [32, 8192]

    qproj_kernel<<<BB, DD>>>(query, Wq, bq);
    score_kernel<<<dim3(TT / TILE_T, BB), 256>>>(value, Wv, bv, av, sbias);
    scan_kernel<<<BB, 256>>>(prev, out_align);
    ctx_reduce_kernel<<<dim3(32, BB), 256>>>(value, out_align);
    ctx_sum_kernel<<<BB, VD>>>();
    ctx_final_kernel<<<BB, DD>>>(Wv, bv, out_ctx);
}

// round 5
// speedup vs baseline: 2.5207x; 2.5207x over previous
#include <cuda_runtime.h>
#include <cstdint>
#include <cstddef>

// Problem shapes (fixed)
#define BB   32
#define TT   8192
#define QD   512
#define VD   256
#define DD   128
#define TILE_T 128
#define KCH    32            // k-floats per SMEM chunk (= 128B = one SW128 atom row)
#define NCHUNK (VD / KCH)    // 8

// tcgen05 is only legal on arch-specific ("a"/family) targets. Non-a passes
// (e.g. a plain compute_103 PTX gencode) compile the FFMA2 fallback body.
#if defined(__CUDA_ARCH__) && (defined(__CUDA_ARCH_FEAT_SM103_ALL) || \
                               defined(__CUDA_ARCH_FEAT_SM100_ALL) || \
                               defined(__CUDA_ARCH_SPECIFIC__)     || \
                               defined(__CUDA_ARCH_FAMILY_SPECIFIC__))
#define HAS_TCGEN05 1
#else
#define HAS_TCGEN05 0
#endif

// ---------------- device scratch (no allocation allowed) ----------------
__device__ float g_q[BB * DD];
__device__ float g_WvT[DD * VD];        // Wv transposed: [d][k]
__device__ float g_score[BB * TT];
__device__ float g_Spart[32][BB][VD];
__device__ float g_S[BB * VD];
__device__ float g_sumA[BB];

// ---------------- generic PTX helpers ----------------
__device__ __forceinline__ uint32_t smem_u32(const void* p) {
    uint32_t a;
    asm("{ .reg .u64 t; cvta.to.shared.u64 t, %1; cvt.u32.u64 %0, t; }" : "=r"(a) : "l"(p));
    return a;
}
__device__ __forceinline__ uint32_t elect_one_pred() {
    uint32_t p;
    asm volatile("{\n\t.reg .pred p;\n\telect.sync _|p, 0xFFFFFFFF;\n\tselp.b32 %0, 1, 0, p;\n\t}" : "=r"(p));
    return p;
}

#define MBARRIER_INIT(addr, cnt) \
    asm volatile("mbarrier.init.shared.b64 [%0], %1;" :: "r"(addr), "r"(cnt) : "memory")

#define MBARRIER_WAIT_PARITY(mbar, parity) do {                                   \
    uint32_t _m = (mbar); uint32_t _p = (parity); uint32_t _d;                    \
    asm volatile("{\n\t.reg .pred p;\n\t"                                         \
        "mbarrier.try_wait.parity.acquire.cta.shared::cta.b64 p, [%1], %2;\n\t"   \
        "selp.b32 %0, 1, 0, p;\n\t}" : "=r"(_d) : "r"(_m), "r"(_p) : "memory");   \
    if (!_d) {                                                                    \
        asm volatile("{\n\t.reg .pred P1;\n\t"                                    \
            "WL_%=:\n\t"                                                          \
            "mbarrier.try_wait.parity.acquire.cta.shared::cta.b64 P1, [%0], %1, 0x989680;\n\t" \
            "@P1 bra.uni WD_%=;\n\t"                                              \
            "bra.uni WL_%=;\n\t"                                                  \
            "WD_%=:\n\t}" :: "r"(_m), "r"(_p) : "memory");                        \
    }                                                                             \
} while (0)

// ---------------- tcgen05 helpers (only referenced from guarded code) ----------------
#define TCGEN05_ALLOC(res_addr, ncols) \
    asm volatile("tcgen05.alloc.cta_group::1.sync.aligned.shared::cta.b32 [%0], %1;" \
                 :: "r"(res_addr), "r"((uint32_t)(ncols)) : "memory")
#define TCGEN05_RELINQ() \
    asm volatile("tcgen05.relinquish_alloc_permit.cta_group::1.sync.aligned;")
#define TCGEN05_DEALLOC(tmem, ncols) \
    asm volatile("tcgen05.dealloc.cta_group::1.sync.aligned.b32 %0, %1;" :: "r"(tmem), "r"((uint32_t)(ncols)))
#define TCGEN05_COMMIT(mbar) \
    asm volatile("tcgen05.commit.cta_group::1.mbarrier::arrive::one.shared::cluster.b64 [%0];" \
                 :: "r"(mbar) : "memory")
#define TCGEN05_FENCE_AFTER() \
    asm volatile("tcgen05.fence::after_thread_sync;" ::: "memory")
#define TCGEN05_WAIT_LD() \
    asm volatile("tcgen05.wait::ld.sync.aligned;" ::: "memory")
#define FENCE_PROXY_ASYNC() \
    asm volatile("fence.proxy.async.shared::cta;" ::: "memory")

#define TCGEN05_LD_X32(r, tmem_addr)                                              \
    asm volatile("tcgen05.ld.sync.aligned.32x32b.x32.b32 "                        \
        "{%0, %1, %2, %3, %4, %5, %6, %7, "                                       \
        " %8, %9, %10, %11, %12, %13, %14, %15, "                                 \
        " %16, %17, %18, %19, %20, %21, %22, %23, "                               \
        " %24, %25, %26, %27, %28, %29, %30, %31}, [%32];"                        \
        : "=r"((r)[0]),  "=r"((r)[1]),  "=r"((r)[2]),  "=r"((r)[3]),              \
          "=r"((r)[4]),  "=r"((r)[5]),  "=r"((r)[6]),  "=r"((r)[7]),              \
          "=r"((r)[8]),  "=r"((r)[9]),  "=r"((r)[10]), "=r"((r)[11]),             \
          "=r"((r)[12]), "=r"((r)[13]), "=r"((r)[14]), "=r"((r)[15]),             \
          "=r"((r)[16]), "=r"((r)[17]), "=r"((r)[18]), "=r"((r)[19]),             \
          "=r"((r)[20]), "=r"((r)[21]), "=r"((r)[22]), "=r"((r)[23]),             \
          "=r"((r)[24]), "=r"((r)[25]), "=r"((r)[26]), "=r"((r)[27]),             \
          "=r"((r)[28]), "=r"((r)[29]), "=r"((r)[30]), "=r"((r)[31])              \
        : "r"(tmem_addr))

// SW128 K-major SMEM descriptor (LBO=1, SBO=64, version=1, layout=SW128)
static __device__ constexpr uint64_t SMEM_DESC_BASE_SW128 =
    (uint64_t(2) << 61) | (uint64_t(1) << 46) | (uint64_t(64) << 32) | (uint64_t(1) << 16);
__device__ __forceinline__ uint64_t make_desc(uint32_t addr) {
    return SMEM_DESC_BASE_SW128 | ((uint64_t)(addr >> 4) & 0x3FFF);
}

#if HAS_TCGEN05
__device__ __forceinline__ void mma_tf32_ss(uint32_t d_tmem, uint64_t a_desc, uint64_t b_desc,
                                            uint32_t idesc, uint32_t enable) {
    asm volatile(
        "{\n\t.reg .pred p;\n\t"
        "setp.ne.u32 p, %4, 0;\n\t"
        "tcgen05.mma.cta_group::1.kind::tf32 [%0], %1, %2, %3, {%5, %5, %5, %5}, p;\n\t}"
        :: "r"(d_tmem), "l"(a_desc), "l"(b_desc), "r"(idesc), "r"(enable), "r"(0u)
        : "memory");
}
#endif

// ---------------- f32x2 packed-FMA helpers (fallback path) ----------------
__device__ __forceinline__ unsigned long long pack2(float lo, float hi) {
    unsigned long long r;
    asm("mov.b64 %0, {%1, %2};" : "=l"(r) : "f"(lo), "f"(hi));
    return r;
}
__device__ __forceinline__ void unpack2(unsigned long long v, float& lo, float& hi) {
    asm("mov.b64 {%0, %1}, %2;" : "=f"(lo), "=f"(hi) : "l"(v));
}
__device__ __forceinline__ void ffma2(unsigned long long& d,
                                      unsigned long long a,
                                      unsigned long long b) {
    asm("fma.rn.f32x2 %0, %1, %2, %0;" : "+l"(d) : "l"(a), "l"(b));
}

// ---------------- kernel A: q = query @ Wq + bq ----------------
__global__ void qproj_kernel(const float* __restrict__ query,
                             const float* __restrict__ Wq,
                             const float* __restrict__ bq) {
    int b = blockIdx.x;
    int d = threadIdx.x;
    float acc = bq[d];
    const float* qr = query + (size_t)b * QD;
#pragma unroll 8
    for (int k = 0; k < QD; k++)
        acc += qr[k] * Wq[(size_t)k * DD + d];
    g_q[b * DD + d] = acc;
}

// ---------------- kernel A2: WvT[d][k] = Wv[k][d] ----------------
__global__ void wvt_kernel(const float* __restrict__ Wv) {
    int d = blockIdx.x;        // 128
    int k = threadIdx.x;       // 256
    g_WvT[d * VD + k] = Wv[(size_t)k * DD + d];
}

// ---------------- kernel B: score GEMM + Bahdanau epilogue ----------------
// score[b,t] = sum_d av[d]*tanh(q[b,d]+bv[d]+(value[b,t,:]@Wv)[d]) + bias
__global__ __launch_bounds__(256) void score_kernel(
    const float* __restrict__ value,
    const float* __restrict__ Wv,
    const float* __restrict__ bv,
    const float* __restrict__ av,
    const float* __restrict__ sbias) {

#if HAS_TCGEN05
    // ======== tcgen05 tf32 path (sm_103a cubin) ========
    __shared__ __align__(1024) char sbuf[2 * 16384];   // A + B chunk tiles
    __shared__ uint32_t s_tmem[1];
    __shared__ __align__(8) unsigned long long s_mbar[1];
    __shared__ float qsh[DD], avsh[DD];
    __shared__ float partial[2][TILE_T];

    int tid = threadIdx.x;
    int wid = tid >> 5, lid = tid & 31;
    int b = blockIdx.y, t0 = blockIdx.x * TILE_T;

    char* vptr = sbuf;
    char* wptr = sbuf + 16384;
    uint32_t v_u32 = smem_u32(vptr);
    uint32_t w_u32 = smem_u32(wptr);
    uint32_t mbar_u32 = smem_u32(&s_mbar[0]);
    uint32_t tptr_u32 = smem_u32(&s_tmem[0]);

    if (tid < DD) {
        qsh[tid]  = g_q[b * DD + tid] + bv[tid];
        avsh[tid] = av[tid];
    }
    if (tid == 0) MBARRIER_INIT(mbar_u32, 1);
    if (wid == 0) {
        TCGEN05_ALLOC(tptr_u32, 128);
        TCGEN05_RELINQ();
    }
    __syncthreads();
    uint32_t tmem = s_tmem[0];

    const float* vrow = value + ((size_t)b * TT + t0) * VD;
    const float* wrow = g_WvT;

    // idesc: dtype=F32(1<<4), atype=TF32(2<<7), btype=TF32(2<<10), N=128, M=128
    const uint32_t idesc = (1u << 4) | (2u << 7) | (2u << 10)
                         | ((DD / 8) << 17) | ((TILE_T / 16) << 24);

    for (int c = 0; c < NCHUNK; c++) {
        // load 128 rows x 32 k-floats for A (value) and B (WvT): 4 float4/thread each
        float4 vr[4], wr[4];
#pragma unroll
        for (int i = 0; i < 4; i++) {
            int j = i * 256 + tid;           // 0..1023 float4 index
            int row = j >> 3;
            int kp  = (j & 7) * 4;
            vr[i] = *(const float4*)(vrow + (size_t)row * VD + c * KCH + kp);
            wr[i] = *(const float4*)(wrow + (size_t)row * VD + c * KCH + kp);
        }
#pragma unroll
        for (int i = 0; i < 4; i++) {
            int j = i * 256 + tid;
            int row = j >> 3;
            int kb  = (j & 7) * 16;
            uint32_t off = row * 128 + kb;
            uint32_t sw = off ^ ((off >> 3) & 0x70);   // SW128 swizzle
            *(float4*)(vptr + sw) = vr[i];
            *(float4*)(wptr + sw) = wr[i];
        }
        __syncthreads();

        if (wid == 0) {
            FENCE_PROXY_ASYNC();
            if (elect_one_pred()) {
                uint64_t a0 = make_desc(v_u32);
                uint64_t b0 = make_desc(w_u32);
#pragma unroll
                for (int s = 0; s < 4; s++)            // 4 x K=8 tf32 steps (+32B = +2 units)
                    mma_tf32_ss(tmem, a0 + s * 2, b0 + s * 2, idesc,
                                (uint32_t)((c > 0) || (s > 0)));
                TCGEN05_COMMIT(mbar_u32);
            }
        }
        MBARRIER_WAIT_PARITY(mbar_u32, (uint32_t)(c & 1));
    }

    TCGEN05_FENCE_AFTER();

    // epilogue: warp w reads subpartition rows 32*(w&3)+lid.
    // warps 0-3 -> col groups 0,1 ; warps 4-7 -> col groups 2,3
    float s = 0.f;
    int g0 = (wid < 4) ? 0 : 2;
#pragma unroll
    for (int gi = 0; gi < 2; gi++) {
        int g = g0 + gi;
        uint32_t dr[32];
        TCGEN05_LD_X32(dr, tmem + g * 32);
        TCGEN05_WAIT_LD();
#pragma unroll
        for (int j = 0; j < 32; j++) {
            int col = g * 32 + j;
            s += avsh[col] * tanhf(qsh[col] + __uint_as_float(dr[j]));
        }
    }
    partial[wid >> 2][(wid & 3) * 32 + lid] = s;
    __syncthreads();
    if (tid < TILE_T)
        g_score[(size_t)b * TT + t0 + tid] = partial[0][tid] + partial[1][tid] + sbias[0];

    __syncthreads();
    if (wid == 0) TCGEN05_DEALLOC(tmem, 128);
    (void)Wv;

#else
    // ======== FFMA2 fallback (non-"a" compilation pass) ========
    __shared__ __align__(16) float bsh[16][DD];        // Wv chunk [k][d]
    __shared__ float vsh[16][TILE_T + 1];              // value chunk, k-major [k][t]

    int b  = blockIdx.y;
    int t0 = blockIdx.x * TILE_T;
    int tid = threadIdx.x;
    int tx = tid & 15;             // 16 column groups (8 d-cols each)
    int ty = tid >> 4;             // 16 row groups   (8 t-rows each)

    unsigned long long acc[8][4];
#pragma unroll
    for (int i = 0; i < 8; i++)
#pragma unroll
        for (int j = 0; j < 4; j++) acc[i][j] = 0ull;

    const float* vptr = value + ((size_t)b * TT + t0) * VD;

    for (int kc = 0; kc < VD; kc += 16) {
#pragma unroll
        for (int r = 0; r < 2; r++) {
            int idx = tid + r * 256;
            int row = idx >> 2;
            int k4  = (idx & 3) * 4;
            float4 vv = *(const float4*)(vptr + (size_t)row * VD + kc + k4);
            vsh[k4 + 0][row] = vv.x;
            vsh[k4 + 1][row] = vv.y;
            vsh[k4 + 2][row] = vv.z;
            vsh[k4 + 3][row] = vv.w;
        }
#pragma unroll
        for (int r = 0; r < 2; r++) {
            int idx = tid + r * 256;
            int kk  = idx >> 5;
            int d4  = (idx & 31) * 4;
            *(float4*)&bsh[kk][d4] = *(const float4*)(Wv + (size_t)(kc + kk) * DD + d4);
        }
        __syncthreads();

#pragma unroll
        for (int kk = 0; kk < 16; kk++) {
            unsigned long long ap[8];
#pragma unroll
            for (int i = 0; i < 8; i++) {
                float a = vsh[kk][ty * 8 + i];
                ap[i] = pack2(a, a);
            }
            unsigned long long bp[4];
#pragma unroll
            for (int j = 0; j < 4; j++)
                bp[j] = *(const unsigned long long*)&bsh[kk][tx * 8 + j * 2];
#pragma unroll
            for (int i = 0; i < 8; i++)
#pragma unroll
                for (int j = 0; j < 4; j++)
                    ffma2(acc[i][j], ap[i], bp[j]);
        }
        __syncthreads();
    }

    float qv[8], avv[8];
#pragma unroll
    for (int j = 0; j < 8; j++) {
        int c = tx * 8 + j;
        qv[j]  = g_q[b * DD + c] + bv[c];
        avv[j] = av[c];
    }
    float part[8];
#pragma unroll
    for (int i = 0; i < 8; i++) {
        float s = 0.f;
#pragma unroll
        for (int j = 0; j < 4; j++) {
            float lo, hi;
            unpack2(acc[i][j], lo, hi);
            s += avv[2 * j]     * tanhf(qv[2 * j]     + lo);
            s += avv[2 * j + 1] * tanhf(qv[2 * j + 1] + hi);
        }
        part[i] = s;
    }
#pragma unroll
    for (int o = 8; o >= 1; o >>= 1)
#pragma unroll
        for (int i = 0; i < 8; i++)
            part[i] += __shfl_down_sync(0xffffffffu, part[i], o, 16);

    if (tx == 0) {
        float bias = *sbias;
#pragma unroll
        for (int i = 0; i < 8; i++)
            g_score[b * TT + t0 + ty * 8 + i] = part[i] + bias;
    }
#endif
}

// ---------------- kernel C: monotonic-attention scan ----------------
__device__ __forceinline__ float sigmoidf_stable(float s) {
    if (s >= 0.f) { float e = expf(-s); return 1.f / (1.f + e); }
    float e = expf(s); return e / (1.f + e);
}

__device__ float block_exscan256(float v, float* sm) {
    float x = v;
#pragma unroll
    for (int o = 1; o < 32; o <<= 1) {
        float y = __shfl_up_sync(0xffffffffu, x, o);
        if ((threadIdx.x & 31) >= o) x += y;
    }
    int warp = threadIdx.x >> 5;
    __syncthreads();
    if ((threadIdx.x & 31) == 31) sm[warp] = x;
    __syncthreads();
    float woff = 0.f;
    for (int w = 0; w < warp; w++) woff += sm[w];
    return woff + x - v;
}

__global__ __launch_bounds__(256) void scan_kernel(
    const float* __restrict__ prev, float* __restrict__ out_align) {
    __shared__ float sm[8];
    const float TINYF = 1.17549435e-38f;
    int b = blockIdx.x;
    int tid = threadIdx.x;
    const float* sc = g_score + (size_t)b * TT;
    const float* pa = prev + (size_t)b * TT;
    int base = tid * 32;

    float suml = 0.f;
    for (int c = 0; c < 32; c++) {
        float p  = sigmoidf_stable(sc[base + c]);
        float om = fminf(fmaxf(1.f - p, TINYF), 1.f);
        suml += logf(om);
    }
    float prefl = block_exscan256(suml, sm);

    float run = 0.f, sumu = 0.f;
    for (int c = 0; c < 32; c++) {
        float p  = sigmoidf_stable(sc[base + c]);
        float om = fminf(fmaxf(1.f - p, TINYF), 1.f);
        float l  = logf(om);
        float cp = expf(prefl + run);
        run += l;
        float u = pa[base + c] / fminf(fmaxf(cp, 1e-10f), 1.f);
        sumu += u;
    }
    float prefu = block_exscan256(sumu, sm);

    run = 0.f;
    float runu = 0.f, suma = 0.f;
    for (int c = 0; c < 32; c++) {
        float p  = sigmoidf_stable(sc[base + c]);
        float om = fminf(fmaxf(1.f - p, TINYF), 1.f);
        float l  = logf(om);
        float cp = expf(prefl + run);
        run += l;
        float u = pa[base + c] / fminf(fmaxf(cp, 1e-10f), 1.f);
        runu += u;
        float al = p * cp * (prefu + runu);
        out_align[(size_t)b * TT + base + c] = al;
        suma += al;
    }
    float prefa = block_exscan256(suma, sm);
    if (tid == 255) g_sumA[b] = prefa + suma;
}

// ---------------- kernel D: partial S = alignment @ value ----------------
__global__ __launch_bounds__(256) void ctx_reduce_kernel(
    const float* __restrict__ value, const float* __restrict__ align) {
    __shared__ float ash[256];
    int tc = blockIdx.x;
    int b  = blockIdx.y;
    int tid = threadIdx.x;
    int t0 = tc * 256;
    ash[tid] = align[(size_t)b * TT + t0 + tid];
    __syncthreads();
    const float* vp = value + ((size_t)b * TT + t0) * VD + tid;
    float acc = 0.f;
#pragma unroll 8
    for (int t = 0; t < 256; t++)
        acc += ash[t] * vp[(size_t)t * VD];
    g_Spart[tc][b][tid] = acc;
}

// ---------------- kernel E1: reduce partials ----------------
__global__ void ctx_sum_kernel() {
    int b = blockIdx.x;
    int k = threadIdx.x;
    float s = 0.f;
#pragma unroll
    for (int c = 0; c < 32; c++) s += g_Spart[c][b][k];
    g_S[b * VD + k] = s;
}

// ---------------- kernel E2: context = S @ Wv + sumA * bv ----------------
__global__ void ctx_final_kernel(const float* __restrict__ Wv,
                                 const float* __restrict__ bv,
                                 float* __restrict__ out_ctx) {
    int b = blockIdx.x;
    int d = threadIdx.x;
    float acc = g_sumA[b] * bv[d];
#pragma unroll 8
    for (int k = 0; k < VD; k++)
        acc += g_S[b * VD + k] * Wv[(size_t)k * DD + d];
    out_ctx[b * DD + d] = acc;
}

// ---------------- launcher ----------------
extern "C" void kernel_launch(void* const* d_in, const int* in_sizes, int n_in,
                              void* d_out, int out_size) {
    (void)in_sizes; (void)n_in; (void)out_size;
    const float* query = (const float*)d_in[0];
    const float* value = (const float*)d_in[1];
    const float* prev  = (const float*)d_in[2];
    const float* Wq    = (const float*)d_in[3];
    const float* bq    = (const float*)d_in[4];
    const float* Wv    = (const float*)d_in[5];
    const float* bv    = (const float*)d_in[6];
    const float* av    = (const float*)d_in[7];
    const float* sbias = (const float*)d_in[8];

    float* out       = (float*)d_out;
    float* out_ctx   = out;                  // [32, 128]
    float* out_align = out + BB * DD;        // [32, 8192]

    qproj_kernel<<<BB, DD>>>(query, Wq, bq);
    wvt_kernel<<<DD, VD>>>(Wv);
    score_kernel<<<dim3(TT / TILE_T, BB), 256>>>(value, Wv, bv, av, sbias);
    scan_kernel<<<BB, 256>>>(prev, out_align);
    ctx_reduce_kernel<<<dim3(32, BB), 256>>>(value, out_align);
    ctx_sum_kernel<<<BB, VD>>>();
    ctx_final_kernel<<<BB, DD>>>(Wv, bv, out_ctx);
}

// round 7
// speedup vs baseline: 2.6412x; 1.0478x over previous
#include <cuda_runtime.h>
#include <cstdint>
#include <cstddef>

// Problem shapes (fixed)
#define BB   32
#define TT   8192
#define QD   512
#define VD   256
#define DD   128
#define TILE_T 128
#define KCH    32            // k-floats per SMEM chunk (= 128B = one SW128 atom row)
#define NCHUNK (VD / KCH)    // 8

// tcgen05 is only legal on arch-specific ("a"/family) targets. Non-a passes
// compile the FFMA2 fallback body.
#if defined(__CUDA_ARCH__) && (defined(__CUDA_ARCH_FEAT_SM103_ALL) || \
                               defined(__CUDA_ARCH_FEAT_SM100_ALL) || \
                               defined(__CUDA_ARCH_SPECIFIC__)     || \
                               defined(__CUDA_ARCH_FAMILY_SPECIFIC__))
#define HAS_TCGEN05 1
#else
#define HAS_TCGEN05 0
#endif

// ---------------- device scratch (no allocation allowed) ----------------
__device__ float g_q[BB * DD];
__device__ float g_WvT[DD * VD];        // Wv transposed: [d][k]
__device__ float g_score[BB * TT];
__device__ __align__(16) float g_Spart[32][BB][VD];
__device__ float g_S[BB * VD];
__device__ float g_sumA[BB];

// ---------------- generic PTX helpers ----------------
__device__ __forceinline__ uint32_t smem_u32(const void* p) {
    uint32_t a;
    asm("{ .reg .u64 t; cvta.to.shared.u64 t, %1; cvt.u32.u64 %0, t; }" : "=r"(a) : "l"(p));
    return a;
}
__device__ __forceinline__ uint32_t elect_one_pred() {
    uint32_t p;
    asm volatile("{\n\t.reg .pred p;\n\telect.sync _|p, 0xFFFFFFFF;\n\tselp.b32 %0, 1, 0, p;\n\t}" : "=r"(p));
    return p;
}

#define MBARRIER_INIT(addr, cnt) \
    asm volatile("mbarrier.init.shared.b64 [%0], %1;" :: "r"(addr), "r"(cnt) : "memory")

#define MBARRIER_WAIT_PARITY(mbar, parity) do {                                   \
    uint32_t _m = (mbar); uint32_t _p = (parity); uint32_t _d;                    \
    asm volatile("{\n\t.reg .pred p;\n\t"                                         \
        "mbarrier.try_wait.parity.acquire.cta.shared::cta.b64 p, [%1], %2;\n\t"   \
        "selp.b32 %0, 1, 0, p;\n\t}" : "=r"(_d) : "r"(_m), "r"(_p) : "memory");   \
    if (!_d) {                                                                    \
        asm volatile("{\n\t.reg .pred P1;\n\t"                                    \
            "WL_%=:\n\t"                                                          \
            "mbarrier.try_wait.parity.acquire.cta.shared::cta.b64 P1, [%0], %1, 0x989680;\n\t" \
            "@P1 bra.uni WD_%=;\n\t"                                              \
            "bra.uni WL_%=;\n\t"                                                  \
            "WD_%=:\n\t}" :: "r"(_m), "r"(_p) : "memory");                        \
    }                                                                             \
} while (0)

// ---------------- tcgen05 helpers (only referenced from guarded code) ----------------
#define TCGEN05_ALLOC(res_addr, ncols) \
    asm volatile("tcgen05.alloc.cta_group::1.sync.aligned.shared::cta.b32 [%0], %1;" \
                 :: "r"(res_addr), "r"((uint32_t)(ncols)) : "memory")
#define TCGEN05_RELINQ() \
    asm volatile("tcgen05.relinquish_alloc_permit.cta_group::1.sync.aligned;")
#define TCGEN05_DEALLOC(tmem, ncols) \
    asm volatile("tcgen05.dealloc.cta_group::1.sync.aligned.b32 %0, %1;" :: "r"(tmem), "r"((uint32_t)(ncols)))
#define TCGEN05_COMMIT(mbar) \
    asm volatile("tcgen05.commit.cta_group::1.mbarrier::arrive::one.shared::cluster.b64 [%0];" \
                 :: "r"(mbar) : "memory")
#define TCGEN05_FENCE_AFTER() \
    asm volatile("tcgen05.fence::after_thread_sync;" ::: "memory")
#define TCGEN05_WAIT_LD() \
    asm volatile("tcgen05.wait::ld.sync.aligned;" ::: "memory")
#define FENCE_PROXY_ASYNC() \
    asm volatile("fence.proxy.async.shared::cta;" ::: "memory")

#define TCGEN05_LD_X32(r, tmem_addr)                                              \
    asm volatile("tcgen05.ld.sync.aligned.32x32b.x32.b32 "                        \
        "{%0, %1, %2, %3, %4, %5, %6, %7, "                                       \
        " %8, %9, %10, %11, %12, %13, %14, %15, "                                 \
        " %16, %17, %18, %19, %20, %21, %22, %23, "                               \
        " %24, %25, %26, %27, %28, %29, %30, %31}, [%32];"                        \
        : "=r"((r)[0]),  "=r"((r)[1]),  "=r"((r)[2]),  "=r"((r)[3]),              \
          "=r"((r)[4]),  "=r"((r)[5]),  "=r"((r)[6]),  "=r"((r)[7]),              \
          "=r"((r)[8]),  "=r"((r)[9]),  "=r"((r)[10]), "=r"((r)[11]),             \
          "=r"((r)[12]), "=r"((r)[13]), "=r"((r)[14]), "=r"((r)[15]),             \
          "=r"((r)[16]), "=r"((r)[17]), "=r"((r)[18]), "=r"((r)[19]),             \
          "=r"((r)[20]), "=r"((r)[21]), "=r"((r)[22]), "=r"((r)[23]),             \
          "=r"((r)[24]), "=r"((r)[25]), "=r"((r)[26]), "=r"((r)[27]),             \
          "=r"((r)[28]), "=r"((r)[29]), "=r"((r)[30]), "=r"((r)[31])              \
        : "r"(tmem_addr))

// SW128 K-major SMEM descriptor (LBO=1, SBO=64, version=1, layout=SW128)
static __device__ constexpr uint64_t SMEM_DESC_BASE_SW128 =
    (uint64_t(2) << 61) | (uint64_t(1) << 46) | (uint64_t(64) << 32) | (uint64_t(1) << 16);
__device__ __forceinline__ uint64_t make_desc(uint32_t addr) {
    return SMEM_DESC_BASE_SW128 | ((uint64_t)(addr >> 4) & 0x3FFF);
}

#if HAS_TCGEN05
__device__ __forceinline__ void mma_tf32_ss(uint32_t d_tmem, uint64_t a_desc, uint64_t b_desc,
                                            uint32_t idesc, uint32_t enable) {
    asm volatile(
        "{\n\t.reg .pred p;\n\t"
        "setp.ne.u32 p, %4, 0;\n\t"
        "tcgen05.mma.cta_group::1.kind::tf32 [%0], %1, %2, %3, {%5, %5, %5, %5}, p;\n\t}"
        :: "r"(d_tmem), "l"(a_desc), "l"(b_desc), "r"(idesc), "r"(enable), "r"(0u)
        : "memory");
}
#endif

// ---------------- f32x2 packed-FMA helpers (fallback path) ----------------
__device__ __forceinline__ unsigned long long pack2(float lo, float hi) {
    unsigned long long r;
    asm("mov.b64 %0, {%1, %2};" : "=l"(r) : "f"(lo), "f"(hi));
    return r;
}
__device__ __forceinline__ void unpack2(unsigned long long v, float& lo, float& hi) {
    asm("mov.b64 {%0, %1}, %2;" : "=f"(lo), "=f"(hi) : "l"(v));
}
__device__ __forceinline__ void ffma2(unsigned long long& d,
                                      unsigned long long a,
                                      unsigned long long b) {
    asm("fma.rn.f32x2 %0, %1, %2, %0;" : "+l"(d) : "l"(a), "l"(b));
}

// ---------------- kernel A: q = query @ Wq + bq ----------------
__global__ void qproj_kernel(const float* __restrict__ query,
                             const float* __restrict__ Wq,
                             const float* __restrict__ bq) {
    int b = blockIdx.x;
    int d = threadIdx.x;
    const float* qr = query + (size_t)b * QD;
    float a0 = 0.f, a1 = 0.f, a2 = 0.f, a3 = 0.f;
#pragma unroll 4
    for (int k = 0; k < QD; k += 4) {
        a0 += qr[k + 0] * Wq[(size_t)(k + 0) * DD + d];
        a1 += qr[k + 1] * Wq[(size_t)(k + 1) * DD + d];
        a2 += qr[k + 2] * Wq[(size_t)(k + 2) * DD + d];
        a3 += qr[k + 3] * Wq[(size_t)(k + 3) * DD + d];
    }
    g_q[b * DD + d] = bq[d] + ((a0 + a1) + (a2 + a3));
}

// ---------------- kernel A2: WvT[d][k] = Wv[k][d] ----------------
__global__ void wvt_kernel(const float* __restrict__ Wv) {
    int d = blockIdx.x;        // 128
    int k = threadIdx.x;       // 256
    g_WvT[d * VD + k] = Wv[(size_t)k * DD + d];
}

// ---------------- kernel B: score GEMM + Bahdanau epilogue ----------------
// score[b,t] = sum_d av[d]*tanh(q[b,d]+bv[d]+(value[b,t,:]@Wv)[d]) + bias
__global__ __launch_bounds__(256) void score_kernel(
    const float* __restrict__ value,
    const float* __restrict__ Wv,
    const float* __restrict__ bv,
    const float* __restrict__ av,
    const float* __restrict__ sbias) {

#if HAS_TCGEN05
    // ======== tcgen05 tf32 path, double-buffered, 2 mbarriers (sm_103a) ========
    extern __shared__ char dynraw[];
    __shared__ uint32_t s_tmem[1];
    __shared__ __align__(8) unsigned long long s_mbar[2];   // one per SMEM buffer
    __shared__ float qsh[DD], avsh[DD];
    __shared__ float partial[2][TILE_T];

    char* dbase = (char*)(((uintptr_t)dynraw + 1023) & ~(uintptr_t)1023);

    int tid = threadIdx.x;
    int wid = tid >> 5, lid = tid & 31;
    int b = blockIdx.y, t0 = blockIdx.x * TILE_T;

    uint32_t mbar0 = smem_u32(&s_mbar[0]);
    uint32_t mbar1 = smem_u32(&s_mbar[1]);
    uint32_t tptr_u32 = smem_u32(&s_tmem[0]);

    if (tid < DD) {
        qsh[tid]  = g_q[b * DD + tid] + bv[tid];
        avsh[tid] = av[tid];
    }
    if (tid == 0) {
        MBARRIER_INIT(mbar0, 1);
        MBARRIER_INIT(mbar1, 1);
    }
    if (wid == 0) {
        TCGEN05_ALLOC(tptr_u32, 128);
        TCGEN05_RELINQ();
    }
    __syncthreads();
    uint32_t tmem = s_tmem[0];

    const float* vrow = value + ((size_t)b * TT + t0) * VD;
    const float* wrow = g_WvT;

    // idesc: dtype=F32(1<<4), atype=TF32(2<<7), btype=TF32(2<<10), N=128, M=128
    const uint32_t idesc = (1u << 4) | (2u << 7) | (2u << 10)
                         | ((DD / 8) << 17) | ((TILE_T / 16) << 24);

    float4 vr[4], wr[4];
    auto load_regs = [&](int c) {
#pragma unroll
        for (int i = 0; i < 4; i++) {
            int j = i * 256 + tid;           // 0..1023 float4 index
            int row = j >> 3;
            int kp  = (j & 7) * 4;
            vr[i] = *(const float4*)(vrow + (size_t)row * VD + c * KCH + kp);
            wr[i] = *(const float4*)(wrow + (size_t)row * VD + c * KCH + kp);
        }
    };
    auto store_regs = [&](char* vb, char* wb) {
#pragma unroll
        for (int i = 0; i < 4; i++) {
            int j = i * 256 + tid;
            int row = j >> 3;
            int kb  = (j & 7) * 16;
            uint32_t off = row * 128 + kb;
            uint32_t sw = off ^ ((off >> 3) & 0x70);   // SW128 swizzle
            *(float4*)(vb + sw) = vr[i];
            *(float4*)(wb + sw) = wr[i];
        }
    };

    load_regs(0);
    for (int c = 0; c < NCHUNK; c++) {
        int buf = c & 1;
        uint32_t mb = buf ? mbar1 : mbar0;
        // buffer `buf` was last committed at chunk c-2 = phase (c>>1)-1 on THIS barrier.
        // At this point at most that phase has been committed here -> no parity aliasing.
        if (c >= 2) MBARRIER_WAIT_PARITY(mb, (uint32_t)(((c >> 1) - 1) & 1));
        char* vb = dbase + buf * 32768;
        char* wb = vb + 16384;
        store_regs(vb, wb);
        __syncthreads();
        if (c + 1 < NCHUNK) load_regs(c + 1);    // LDGs overlap with this chunk's MMAs
        if (wid == 0) {
            FENCE_PROXY_ASYNC();
            if (elect_one_pred()) {
                uint64_t a0 = make_desc(smem_u32(vb));
                uint64_t b0 = make_desc(smem_u32(wb));
#pragma unroll
                for (int s = 0; s < 4; s++)      // 4 x K=8 tf32 steps (+32B = +2 units)
                    mma_tf32_ss(tmem, a0 + s * 2, b0 + s * 2, idesc,
                                (uint32_t)((c > 0) || (s > 0)));
                TCGEN05_COMMIT(mb);              // completes phase c>>1 on mbar[buf]
            }
        }
    }
    // drain: last commit on each barrier is phase 3 (parity 1)
    MBARRIER_WAIT_PARITY(mbar0, 1u);
    MBARRIER_WAIT_PARITY(mbar1, 1u);

    TCGEN05_FENCE_AFTER();

    // epilogue: warp w reads subpartition rows 32*(w&3)+lid.
    // warps 0-3 -> col groups 0,1 ; warps 4-7 -> col groups 2,3
    float s = 0.f;
    int g0 = (wid < 4) ? 0 : 2;
#pragma unroll
    for (int gi = 0; gi < 2; gi++) {
        int g = g0 + gi;
        uint32_t dr[32];
        TCGEN05_LD_X32(dr, tmem + g * 32);
        TCGEN05_WAIT_LD();
#pragma unroll
        for (int j = 0; j < 32; j++) {
            int col = g * 32 + j;
            s += avsh[col] * tanhf(qsh[col] + __uint_as_float(dr[j]));
        }
    }
    partial[wid >> 2][(wid & 3) * 32 + lid] = s;
    __syncthreads();
    if (tid < TILE_T)
        g_score[(size_t)b * TT + t0 + tid] = partial[0][tid] + partial[1][tid] + sbias[0];

    __syncthreads();
    if (wid == 0) TCGEN05_DEALLOC(tmem, 128);
    (void)Wv;

#else
    // ======== FFMA2 fallback (non-"a" compilation pass) ========
    __shared__ __align__(16) float bsh[16][DD];
    __shared__ float vsh[16][TILE_T + 1];

    int b  = blockIdx.y;
    int t0 = blockIdx.x * TILE_T;
    int tid = threadIdx.x;
    int tx = tid & 15;
    int ty = tid >> 4;

    unsigned long long acc[8][4];
#pragma unroll
    for (int i = 0; i < 8; i++)
#pragma unroll
        for (int j = 0; j < 4; j++) acc[i][j] = 0ull;

    const float* vptr = value + ((size_t)b * TT + t0) * VD;

    for (int kc = 0; kc < VD; kc += 16) {
#pragma unroll
        for (int r = 0; r < 2; r++) {
            int idx = tid + r * 256;
            int row = idx >> 2;
            int k4  = (idx & 3) * 4;
            float4 vv = *(const float4*)(vptr + (size_t)row * VD + kc + k4);
            vsh[k4 + 0][row] = vv.x;
            vsh[k4 + 1][row] = vv.y;
            vsh[k4 + 2][row] = vv.z;
            vsh[k4 + 3][row] = vv.w;
        }
#pragma unroll
        for (int r = 0; r < 2; r++) {
            int idx = tid + r * 256;
            int kk  = idx >> 5;
            int d4  = (idx & 31) * 4;
            *(float4*)&bsh[kk][d4] = *(const float4*)(Wv + (size_t)(kc + kk) * DD + d4);
        }
        __syncthreads();

#pragma unroll
        for (int kk = 0; kk < 16; kk++) {
            unsigned long long ap[8];
#pragma unroll
            for (int i = 0; i < 8; i++) {
                float a = vsh[kk][ty * 8 + i];
                ap[i] = pack2(a, a);
            }
            unsigned long long bp[4];
#pragma unroll
            for (int j = 0; j < 4; j++)
                bp[j] = *(const unsigned long long*)&bsh[kk][tx * 8 + j * 2];
#pragma unroll
            for (int i = 0; i < 8; i++)
#pragma unroll
                for (int j = 0; j < 4; j++)
                    ffma2(acc[i][j], ap[i], bp[j]);
        }
        __syncthreads();
    }

    float qv[8], avv[8];
#pragma unroll
    for (int j = 0; j < 8; j++) {
        int c = tx * 8 + j;
        qv[j]  = g_q[b * DD + c] + bv[c];
        avv[j] = av[c];
    }
    float part[8];
#pragma unroll
    for (int i = 0; i < 8; i++) {
        float s = 0.f;
#pragma unroll
        for (int j = 0; j < 4; j++) {
            float lo, hi;
            unpack2(acc[i][j], lo, hi);
            s += avv[2 * j]     * tanhf(qv[2 * j]     + lo);
            s += avv[2 * j + 1] * tanhf(qv[2 * j + 1] + hi);
        }
        part[i] = s;
    }
#pragma unroll
    for (int o = 8; o >= 1; o >>= 1)
#pragma unroll
        for (int i = 0; i < 8; i++)
            part[i] += __shfl_down_sync(0xffffffffu, part[i], o, 16);

    if (tx == 0) {
        float bias = *sbias;
#pragma unroll
        for (int i = 0; i < 8; i++)
            g_score[b * TT + t0 + ty * 8 + i] = part[i] + bias;
    }
#endif
}

// ---------------- kernel C: monotonic-attention scan ----------------
// 512 threads, 16 contiguous elements per thread, everything register-resident.
__device__ __forceinline__ float block_exscan512(float tsum, float* sh) {
    int lane = threadIdx.x & 31, wid = threadIdx.x >> 5;   // 16 warps
    float x = tsum;
#pragma unroll
    for (int o = 1; o < 32; o <<= 1) {
        float y = __shfl_up_sync(0xffffffffu, x, o);
        if (lane >= o) x += y;
    }
    __syncthreads();                        // protect sh reuse
    if (lane == 31) sh[wid] = x;
    __syncthreads();
    if (wid == 0) {
        float v = (lane < 16) ? sh[lane] : 0.f;
        float xx = v;
#pragma unroll
        for (int o = 1; o < 32; o <<= 1) {
            float y = __shfl_up_sync(0xffffffffu, xx, o);
            if (lane >= o) xx += y;
        }
        if (lane < 16) sh[lane] = xx - v;   // exclusive warp offsets
    }
    __syncthreads();
    return sh[wid] + (x - tsum);            // exclusive prefix for this thread
}

__global__ __launch_bounds__(512) void scan_kernel(
    const float* __restrict__ prev, float* __restrict__ out_align) {
    __shared__ float sh[32];
    const float LOGTINY = -87.336544f;      // log(float32 TINY)
    int b = blockIdx.x;
    int tid = threadIdx.x;
    int base = tid * 16;
    const float* sc = g_score + (size_t)b * TT;
    const float* pa = prev + (size_t)b * TT;

    float s[16], pv[16];
#pragma unroll
    for (int i = 0; i < 4; i++) {
        *(float4*)&s[i * 4]  = *(const float4*)(sc + base + i * 4);
        *(float4*)&pv[i * 4] = *(const float4*)(pa + base + i * 4);
    }

    // p = sigmoid(s);  l = log(clip(1-p, TINY, 1)) = max(-(max(s,0)+log1p(e^{-|s|})), logTINY)
    float p[16], l[16];
#pragma unroll
    for (int i = 0; i < 16; i++) {
        float si = s[i];
        float e  = expf(-fabsf(si));
        float den = 1.f + e;
        p[i] = (si >= 0.f) ? (1.f / den) : (e / den);
        l[i] = fmaxf(-(fmaxf(si, 0.f) + log1pf(e)), LOGTINY);
    }

    // inclusive scan of l in-place
#pragma unroll
    for (int i = 1; i < 16; i++) l[i] += l[i - 1];
    float prefl = block_exscan512(l[15], sh);

    // cp_i = exp(exclusive cumsum of l); u_i = prev_i / clip(cp_i, 1e-10, 1)
    float cp[16];
#pragma unroll
    for (int i = 0; i < 16; i++) {
        cp[i] = expf(prefl + (i ? l[i - 1] : 0.f));
        pv[i] = pv[i] / fmaxf(cp[i], 1e-10f);
    }
    // inclusive scan of u in-place
#pragma unroll
    for (int i = 1; i < 16; i++) pv[i] += pv[i - 1];
    float prefu = block_exscan512(pv[15], sh);

    // alignment = p * cp * inclusive_cumsum(u)
    float asum = 0.f;
#pragma unroll
    for (int i = 0; i < 16; i++) {
        float al = p[i] * cp[i] * (prefu + pv[i]);
        s[i] = al;                           // reuse s as output staging
        asum += al;
    }
#pragma unroll
    for (int i = 0; i < 4; i++)
        *(float4*)(out_align + (size_t)b * TT + base + i * 4) = *(float4*)&s[i * 4];

    float prefa = block_exscan512(asum, sh);
    if (tid == 511) g_sumA[b] = prefa + asum;
}

// ---------------- kernel D: partial S = alignment @ value (float4 over k) ----------------
__global__ __launch_bounds__(256) void ctx_reduce_kernel(
    const float* __restrict__ value, const float* __restrict__ align) {
    __shared__ float ash[256];
    __shared__ float4 red[3][64];
    int tc = blockIdx.x;
    int b  = blockIdx.y;
    int tid = threadIdx.x;
    int k4 = tid & 63, tr = tid >> 6;       // 64 float4 cols x 4 t-offsets
    int t0 = tc * 256;
    ash[tid] = align[(size_t)b * TT + t0 + tid];
    __syncthreads();
    const float4* vp = (const float4*)(value + ((size_t)b * TT + t0) * VD);
    float4 acc = make_float4(0.f, 0.f, 0.f, 0.f);
#pragma unroll 8
    for (int t = tr; t < 256; t += 4) {
        float a = ash[t];
        float4 v = vp[(size_t)t * 64 + k4];
        acc.x = fmaf(a, v.x, acc.x);
        acc.y = fmaf(a, v.y, acc.y);
        acc.z = fmaf(a, v.z, acc.z);
        acc.w = fmaf(a, v.w, acc.w);
    }
    if (tr) red[tr - 1][k4] = acc;
    __syncthreads();
    if (tr == 0) {
        float4 r1 = red[0][k4], r2 = red[1][k4], r3 = red[2][k4];
        acc.x += r1.x + r2.x + r3.x;
        acc.y += r1.y + r2.y + r3.y;
        acc.z += r1.z + r2.z + r3.z;
        acc.w += r1.w + r2.w + r3.w;
        *(float4*)&g_Spart[tc][b][k4 * 4] = acc;
    }
}

// ---------------- kernel E1: reduce partials ----------------
__global__ void ctx_sum_kernel() {
    int b = blockIdx.x;
    int k = threadIdx.x;
    float s = 0.f;
#pragma unroll
    for (int c = 0; c < 32; c++) s += g_Spart[c][b][k];
    g_S[b * VD + k] = s;
}

// ---------------- kernel E2: context = S @ Wv + sumA * bv ----------------
__global__ void ctx_final_kernel(const float* __restrict__ Wv,
                                 const float* __restrict__ bv,
                                 float* __restrict__ out_ctx) {
    int b = blockIdx.x;
    int d = threadIdx.x;
    float acc = g_sumA[b] * bv[d];
#pragma unroll 8
    for (int k = 0; k < VD; k++)
        acc += g_S[b * VD + k] * Wv[(size_t)k * DD + d];
    out_ctx[b * DD + d] = acc;
}

// ---------------- launcher ----------------
extern "C" void kernel_launch(void* const* d_in, const int* in_sizes, int n_in,
                              void* d_out, int out_size) {
    (void)in_sizes; (void)n_in; (void)out_size;
    const float* query = (const float*)d_in[0];
    const float* value = (const float*)d_in[1];
    const float* prev  = (const float*)d_in[2];
    const float* Wq    = (const float*)d_in[3];
    const float* bq    = (const float*)d_in[4];
    const float* Wv    = (const float*)d_in[5];
    const float* bv    = (const float*)d_in[6];
    const float* av    = (const float*)d_in[7];
    const float* sbias = (const float*)d_in[8];

    float* out       = (float*)d_out;
    float* out_ctx   = out;                  // [32, 128]
    float* out_align = out + BB * DD;        // [32, 8192]

    const int SCORE_DYN = 2 * 32768 + 1024;  // double-buffered A/B tiles + align pad
    cudaFuncSetAttribute(score_kernel, cudaFuncAttributeMaxDynamicSharedMemorySize, SCORE_DYN);

    qproj_kernel<<<BB, DD>>>(query, Wq, bq);
    wvt_kernel<<<DD, VD>>>(Wv);
    score_kernel<<<dim3(TT / TILE_T, BB), 256, SCORE_DYN>>>(value, Wv, bv, av, sbias);
    scan_kernel<<<BB, 512>>>(prev, out_align);
    ctx_reduce_kernel<<<dim3(32, BB), 256>>>(value, out_align);
    ctx_sum_kernel<<<BB, VD>>>();
    ctx_final_kernel<<<BB, DD>>>(Wv, bv, out_ctx);
}

// round 8
// speedup vs baseline: 2.8190x; 1.0673x over previous
#include <cuda_runtime.h>
#include <cstdint>
#include <cstddef>

// Problem shapes (fixed)
#define BB   32
#define TT   8192
#define QD   512
#define VD   256
#define DD   128
#define TILE_T 256           // t-rows per score CTA (2 x 128-row MMA accumulators)
#define KCH    32            // k-floats per SMEM chunk (= 128B = one SW128 atom row)
#define NCHUNK (VD / KCH)    // 8
#define STAGE_BYTES (3 * 16384)   // A0 + A1 + B per stage

// tcgen05 is only legal on arch-specific ("a"/family) targets. Non-a passes
// compile the FFMA2 fallback body.
#if defined(__CUDA_ARCH__) && (defined(__CUDA_ARCH_FEAT_SM103_ALL) || \
                               defined(__CUDA_ARCH_FEAT_SM100_ALL) || \
                               defined(__CUDA_ARCH_SPECIFIC__)     || \
                               defined(__CUDA_ARCH_FAMILY_SPECIFIC__))
#define HAS_TCGEN05 1
#else
#define HAS_TCGEN05 0
#endif

// ---------------- device scratch (no allocation allowed) ----------------
__device__ float g_q[BB * DD];
__device__ float g_WvT[DD * VD];        // Wv transposed: [d][k]
__device__ float g_score[BB * TT];
__device__ __align__(16) float g_Spart[32][BB][VD];
__device__ float g_sumA[BB];

// ---------------- generic PTX helpers ----------------
__device__ __forceinline__ uint32_t smem_u32(const void* p) {
    uint32_t a;
    asm("{ .reg .u64 t; cvta.to.shared.u64 t, %1; cvt.u32.u64 %0, t; }" : "=r"(a) : "l"(p));
    return a;
}
__device__ __forceinline__ uint32_t elect_one_pred() {
    uint32_t p;
    asm volatile("{\n\t.reg .pred p;\n\telect.sync _|p, 0xFFFFFFFF;\n\tselp.b32 %0, 1, 0, p;\n\t}" : "=r"(p));
    return p;
}
__device__ __forceinline__ float tanh_fast(float x) {
    float y;
    asm("tanh.approx.f32 %0, %1;" : "=f"(y) : "f"(x));
    return y;
}

#define MBARRIER_INIT(addr, cnt) \
    asm volatile("mbarrier.init.shared.b64 [%0], %1;" :: "r"(addr), "r"(cnt) : "memory")

#define MBARRIER_WAIT_PARITY(mbar, parity) do {                                   \
    uint32_t _m = (mbar); uint32_t _p = (parity); uint32_t _d;                    \
    asm volatile("{\n\t.reg .pred p;\n\t"                                         \
        "mbarrier.try_wait.parity.acquire.cta.shared::cta.b64 p, [%1], %2;\n\t"   \
        "selp.b32 %0, 1, 0, p;\n\t}" : "=r"(_d) : "r"(_m), "r"(_p) : "memory");   \
    if (!_d) {                                                                    \
        asm volatile("{\n\t.reg .pred P1;\n\t"                                    \
            "WL_%=:\n\t"                                                          \
            "mbarrier.try_wait.parity.acquire.cta.shared::cta.b64 P1, [%0], %1, 0x989680;\n\t" \
            "@P1 bra.uni WD_%=;\n\t"                                              \
            "bra.uni WL_%=;\n\t"                                                  \
            "WD_%=:\n\t}" :: "r"(_m), "r"(_p) : "memory");                        \
    }                                                                             \
} while (0)

// ---------------- tcgen05 helpers (only referenced from guarded code) ----------------
#define TCGEN05_ALLOC(res_addr, ncols) \
    asm volatile("tcgen05.alloc.cta_group::1.sync.aligned.shared::cta.b32 [%0], %1;" \
                 :: "r"(res_addr), "r"((uint32_t)(ncols)) : "memory")
#define TCGEN05_RELINQ() \
    asm volatile("tcgen05.relinquish_alloc_permit.cta_group::1.sync.aligned;")
#define TCGEN05_DEALLOC(tmem, ncols) \
    asm volatile("tcgen05.dealloc.cta_group::1.sync.aligned.b32 %0, %1;" :: "r"(tmem), "r"((uint32_t)(ncols)))
#define TCGEN05_COMMIT(mbar) \
    asm volatile("tcgen05.commit.cta_group::1.mbarrier::arrive::one.shared::cluster.b64 [%0];" \
                 :: "r"(mbar) : "memory")
#define TCGEN05_FENCE_AFTER() \
    asm volatile("tcgen05.fence::after_thread_sync;" ::: "memory")
#define TCGEN05_WAIT_LD() \
    asm volatile("tcgen05.wait::ld.sync.aligned;" ::: "memory")
#define FENCE_PROXY_ASYNC() \
    asm volatile("fence.proxy.async.shared::cta;" ::: "memory")

#define TCGEN05_LD_X32(r, tmem_addr)                                              \
    asm volatile("tcgen05.ld.sync.aligned.32x32b.x32.b32 "                        \
        "{%0, %1, %2, %3, %4, %5, %6, %7, "                                       \
        " %8, %9, %10, %11, %12, %13, %14, %15, "                                 \
        " %16, %17, %18, %19, %20, %21, %22, %23, "                               \
        " %24, %25, %26, %27, %28, %29, %30, %31}, [%32];"                        \
        : "=r"((r)[0]),  "=r"((r)[1]),  "=r"((r)[2]),  "=r"((r)[3]),              \
          "=r"((r)[4]),  "=r"((r)[5]),  "=r"((r)[6]),  "=r"((r)[7]),              \
          "=r"((r)[8]),  "=r"((r)[9]),  "=r"((r)[10]), "=r"((r)[11]),             \
          "=r"((r)[12]), "=r"((r)[13]), "=r"((r)[14]), "=r"((r)[15]),             \
          "=r"((r)[16]), "=r"((r)[17]), "=r"((r)[18]), "=r"((r)[19]),             \
          "=r"((r)[20]), "=r"((r)[21]), "=r"((r)[22]), "=r"((r)[23]),             \
          "=r"((r)[24]), "=r"((r)[25]), "=r"((r)[26]), "=r"((r)[27]),             \
          "=r"((r)[28]), "=r"((r)[29]), "=r"((r)[30]), "=r"((r)[31])              \
        : "r"(tmem_addr))

// SW128 K-major SMEM descriptor (LBO=1, SBO=64, version=1, layout=SW128)
static __device__ constexpr uint64_t SMEM_DESC_BASE_SW128 =
    (uint64_t(2) << 61) | (uint64_t(1) << 46) | (uint64_t(64) << 32) | (uint64_t(1) << 16);
__device__ __forceinline__ uint64_t make_desc(uint32_t addr) {
    return SMEM_DESC_BASE_SW128 | ((uint64_t)(addr >> 4) & 0x3FFF);
}

#if HAS_TCGEN05
__device__ __forceinline__ void mma_tf32_ss(uint32_t d_tmem, uint64_t a_desc, uint64_t b_desc,
                                            uint32_t idesc, uint32_t enable) {
    asm volatile(
        "{\n\t.reg .pred p;\n\t"
        "setp.ne.u32 p, %4, 0;\n\t"
        "tcgen05.mma.cta_group::1.kind::tf32 [%0], %1, %2, %3, {%5, %5, %5, %5}, p;\n\t}"
        :: "r"(d_tmem), "l"(a_desc), "l"(b_desc), "r"(idesc), "r"(enable), "r"(0u)
        : "memory");
}
#endif

// ---------------- f32x2 packed-FMA helpers (fallback path) ----------------
__device__ __forceinline__ unsigned long long pack2(float lo, float hi) {
    unsigned long long r;
    asm("mov.b64 %0, {%1, %2};" : "=l"(r) : "f"(lo), "f"(hi));
    return r;
}
__device__ __forceinline__ void unpack2(unsigned long long v, float& lo, float& hi) {
    asm("mov.b64 {%0, %1}, %2;" : "=f"(lo), "=f"(hi) : "l"(v));
}
__device__ __forceinline__ void ffma2(unsigned long long& d,
                                      unsigned long long a,
                                      unsigned long long b) {
    asm("fma.rn.f32x2 %0, %1, %2, %0;" : "+l"(d) : "l"(a), "l"(b));
}

// ---------------- kernel A: q = query @ Wq + bq ----------------
__global__ void qproj_kernel(const float* __restrict__ query,
                             const float* __restrict__ Wq,
                             const float* __restrict__ bq) {
    int b = blockIdx.x;
    int d = threadIdx.x;
    const float* qr = query + (size_t)b * QD;
    float a0 = 0.f, a1 = 0.f, a2 = 0.f, a3 = 0.f;
#pragma unroll 4
    for (int k = 0; k < QD; k += 4) {
        a0 += qr[k + 0] * Wq[(size_t)(k + 0) * DD + d];
        a1 += qr[k + 1] * Wq[(size_t)(k + 1) * DD + d];
        a2 += qr[k + 2] * Wq[(size_t)(k + 2) * DD + d];
        a3 += qr[k + 3] * Wq[(size_t)(k + 3) * DD + d];
    }
    g_q[b * DD + d] = bq[d] + ((a0 + a1) + (a2 + a3));
}

// ---------------- kernel A2: WvT[d][k] = Wv[k][d] ----------------
__global__ void wvt_kernel(const float* __restrict__ Wv) {
    int d = blockIdx.x;        // 128
    int k = threadIdx.x;       // 256
    g_WvT[d * VD + k] = Wv[(size_t)k * DD + d];
}

// ---------------- kernel B: score GEMM + Bahdanau epilogue ----------------
// score[b,t] = sum_d av[d]*tanh(q[b,d]+bv[d]+(value[b,t,:]@Wv)[d]) + bias
__global__ __launch_bounds__(256) void score_kernel(
    const float* __restrict__ value,
    const float* __restrict__ Wv,
    const float* __restrict__ bv,
    const float* __restrict__ av,
    const float* __restrict__ sbias) {

#if HAS_TCGEN05
    // ======== tcgen05 tf32, 256-row tile, dual accumulators, 2-stage pipe ========
    extern __shared__ char dynraw[];
    __shared__ uint32_t s_tmem[1];
    __shared__ __align__(8) unsigned long long s_mbar[2];   // one per stage buffer
    __shared__ float qsh[DD], avsh[DD];

    char* dbase = (char*)(((uintptr_t)dynraw + 1023) & ~(uintptr_t)1023);

    int tid = threadIdx.x;
    int wid = tid >> 5, lid = tid & 31;
    int b = blockIdx.y, t0 = blockIdx.x * TILE_T;

    uint32_t mbar0 = smem_u32(&s_mbar[0]);
    uint32_t mbar1 = smem_u32(&s_mbar[1]);
    uint32_t tptr_u32 = smem_u32(&s_tmem[0]);

    if (tid < DD) {
        qsh[tid]  = g_q[b * DD + tid] + bv[tid];
        avsh[tid] = av[tid];
    }
    if (tid == 0) {
        MBARRIER_INIT(mbar0, 1);
        MBARRIER_INIT(mbar1, 1);
    }
    if (wid == 0) {
        TCGEN05_ALLOC(tptr_u32, 256);       // D0 @ +0, D1 @ +128
        TCGEN05_RELINQ();
    }
    __syncthreads();
    uint32_t tmem = s_tmem[0];

    const float* vrow = value + ((size_t)b * TT + t0) * VD;
    const float* wrow = g_WvT;

    // idesc: dtype=F32(1<<4), atype=TF32(2<<7), btype=TF32(2<<10), N=128, M=128
    const uint32_t idesc = (1u << 4) | (2u << 7) | (2u << 10)
                         | ((DD / 8) << 17) | (8u << 24);

    float4 vr[8], wr[4];
    auto load_regs = [&](int c) {
#pragma unroll
        for (int i = 0; i < 8; i++) {        // 2048 float4: 256 value rows x 8
            int j = i * 256 + tid;
            int row = j >> 3;                // 0..255
            int kp  = (j & 7) * 4;
            vr[i] = *(const float4*)(vrow + (size_t)row * VD + c * KCH + kp);
        }
#pragma unroll
        for (int i = 0; i < 4; i++) {        // 1024 float4: 128 WvT rows x 8
            int j = i * 256 + tid;
            int row = j >> 3;                // 0..127
            int kp  = (j & 7) * 4;
            wr[i] = *(const float4*)(wrow + (size_t)row * VD + c * KCH + kp);
        }
    };
    auto store_regs = [&](char* stage) {
        char* a0p = stage;                   // A0: value rows 0-127
        char* a1p = stage + 16384;           // A1: value rows 128-255
        char* bp  = stage + 32768;           // B : WvT rows 0-127
#pragma unroll
        for (int i = 0; i < 8; i++) {
            int j = i * 256 + tid;
            int row = j >> 3;
            uint32_t off = (row & 127) * 128 + (j & 7) * 16;
            uint32_t sw = off ^ ((off >> 3) & 0x70);
            *(float4*)(((row >> 7) ? a1p : a0p) + sw) = vr[i];
        }
#pragma unroll
        for (int i = 0; i < 4; i++) {
            int j = i * 256 + tid;
            int row = j >> 3;
            uint32_t off = row * 128 + (j & 7) * 16;
            uint32_t sw = off ^ ((off >> 3) & 0x70);
            *(float4*)(bp + sw) = wr[i];
        }
    };

    load_regs(0);
    for (int c = 0; c < NCHUNK; c++) {
        int buf = c & 1;
        uint32_t mb = buf ? mbar1 : mbar0;
        // buffer `buf` last committed at chunk c-2 = phase (c>>1)-1 on THIS barrier.
        if (c >= 2) MBARRIER_WAIT_PARITY(mb, (uint32_t)(((c >> 1) - 1) & 1));
        char* stage = dbase + buf * STAGE_BYTES;
        store_regs(stage);
        __syncthreads();
        if (c + 1 < NCHUNK) load_regs(c + 1);     // overlap next LDGs with MMAs
        if (wid == 0) {
            FENCE_PROXY_ASYNC();
            if (elect_one_pred()) {
                uint64_t a0 = make_desc(smem_u32(stage));
                uint64_t a1 = make_desc(smem_u32(stage + 16384));
                uint64_t b0 = make_desc(smem_u32(stage + 32768));
#pragma unroll
                for (int s = 0; s < 4; s++) {     // 4 x K=8 tf32 steps (+32B = +2 units)
                    uint32_t en = (uint32_t)((c > 0) || (s > 0));
                    mma_tf32_ss(tmem,        a0 + s * 2, b0 + s * 2, idesc, en);
                    mma_tf32_ss(tmem + 128,  a1 + s * 2, b0 + s * 2, idesc, en);
                }
                TCGEN05_COMMIT(mb);
            }
        }
    }
    // drain: last commit on each barrier is phase 3 (parity 1)
    MBARRIER_WAIT_PARITY(mbar0, 1u);
    MBARRIER_WAIT_PARITY(mbar1, 1u);

    TCGEN05_FENCE_AFTER();

    // epilogue: warp w -> accumulator part=w>>2 (D0/D1), subpartition w&3.
    // lane owns one t-row; sum over all 128 cols in-lane, no cross-lane reduce.
    int part = wid >> 2;
    float s = 0.f;
#pragma unroll
    for (int g = 0; g < 4; g++) {
        uint32_t dr[32];
        TCGEN05_LD_X32(dr, tmem + part * 128 + g * 32);
        TCGEN05_WAIT_LD();
#pragma unroll
        for (int j = 0; j < 32; j++) {
            int col = g * 32 + j;
            s += avsh[col] * tanh_fast(qsh[col] + __uint_as_float(dr[j]));
        }
    }
    int trow = part * 128 + (wid & 3) * 32 + lid;
    g_score[(size_t)b * TT + t0 + trow] = s + sbias[0];

    __syncthreads();
    if (wid == 0) TCGEN05_DEALLOC(tmem, 256);
    (void)Wv;

#else
    // ======== FFMA2 fallback (non-"a" compilation pass): two 128-row halves ====
    __shared__ __align__(16) float bsh[16][DD];
    __shared__ float vsh[16][128 + 1];

    int b  = blockIdx.y;
    int tid = threadIdx.x;
    int tx = tid & 15;
    int ty = tid >> 4;

    for (int half = 0; half < 2; half++) {
        int t0 = blockIdx.x * TILE_T + half * 128;

        unsigned long long acc[8][4];
#pragma unroll
        for (int i = 0; i < 8; i++)
#pragma unroll
            for (int j = 0; j < 4; j++) acc[i][j] = 0ull;

        const float* vptr = value + ((size_t)b * TT + t0) * VD;

        for (int kc = 0; kc < VD; kc += 16) {
            __syncthreads();
#pragma unroll
            for (int r = 0; r < 2; r++) {
                int idx = tid + r * 256;
                int row = idx >> 2;
                int k4  = (idx & 3) * 4;
                float4 vv = *(const float4*)(vptr + (size_t)row * VD + kc + k4);
                vsh[k4 + 0][row] = vv.x;
                vsh[k4 + 1][row] = vv.y;
                vsh[k4 + 2][row] = vv.z;
                vsh[k4 + 3][row] = vv.w;
            }
#pragma unroll
            for (int r = 0; r < 2; r++) {
                int idx = tid + r * 256;
                int kk  = idx >> 5;
                int d4  = (idx & 31) * 4;
                *(float4*)&bsh[kk][d4] = *(const float4*)(Wv + (size_t)(kc + kk) * DD + d4);
            }
            __syncthreads();

#pragma unroll
            for (int kk = 0; kk < 16; kk++) {
                unsigned long long ap[8];
#pragma unroll
                for (int i = 0; i < 8; i++) {
                    float a = vsh[kk][ty * 8 + i];
                    ap[i] = pack2(a, a);
                }
                unsigned long long bp[4];
#pragma unroll
                for (int j = 0; j < 4; j++)
                    bp[j] = *(const unsigned long long*)&bsh[kk][tx * 8 + j * 2];
#pragma unroll
                for (int i = 0; i < 8; i++)
#pragma unroll
                    for (int j = 0; j < 4; j++)
                        ffma2(acc[i][j], ap[i], bp[j]);
            }
        }

        float qv[8], avv[8];
#pragma unroll
        for (int j = 0; j < 8; j++) {
            int c = tx * 8 + j;
            qv[j]  = g_q[b * DD + c] + bv[c];
            avv[j] = av[c];
        }
        float part[8];
#pragma unroll
        for (int i = 0; i < 8; i++) {
            float s = 0.f;
#pragma unroll
            for (int j = 0; j < 4; j++) {
                float lo, hi;
                unpack2(acc[i][j], lo, hi);
                s += avv[2 * j]     * tanh_fast(qv[2 * j]     + lo);
                s += avv[2 * j + 1] * tanh_fast(qv[2 * j + 1] + hi);
            }
            part[i] = s;
        }
#pragma unroll
        for (int o = 8; o >= 1; o >>= 1)
#pragma unroll
            for (int i = 0; i < 8; i++)
                part[i] += __shfl_down_sync(0xffffffffu, part[i], o, 16);

        if (tx == 0) {
            float bias = *sbias;
#pragma unroll
            for (int i = 0; i < 8; i++)
                g_score[b * TT + t0 + ty * 8 + i] = part[i] + bias;
        }
        __syncthreads();
    }
#endif
}

// ---------------- kernel C: monotonic-attention scan ----------------
__device__ __forceinline__ float block_exscan512(float tsum, float* sh) {
    int lane = threadIdx.x & 31, wid = threadIdx.x >> 5;   // 16 warps
    float x = tsum;
#pragma unroll
    for (int o = 1; o < 32; o <<= 1) {
        float y = __shfl_up_sync(0xffffffffu, x, o);
        if (lane >= o) x += y;
    }
    __syncthreads();
    if (lane == 31) sh[wid] = x;
    __syncthreads();
    if (wid == 0) {
        float v = (lane < 16) ? sh[lane] : 0.f;
        float xx = v;
#pragma unroll
        for (int o = 1; o < 32; o <<= 1) {
            float y = __shfl_up_sync(0xffffffffu, xx, o);
            if (lane >= o) xx += y;
        }
        if (lane < 16) sh[lane] = xx - v;
    }
    __syncthreads();
    return sh[wid] + (x - tsum);
}

__global__ __launch_bounds__(512) void scan_kernel(
    const float* __restrict__ prev, float* __restrict__ out_align) {
    __shared__ float sh[32];
    const float LOGTINY = -87.336544f;
    int b = blockIdx.x;
    int tid = threadIdx.x;
    int base = tid * 16;
    const float* sc = g_score + (size_t)b * TT;
    const float* pa = prev + (size_t)b * TT;

    float s[16], pv[16];
#pragma unroll
    for (int i = 0; i < 4; i++) {
        *(float4*)&s[i * 4]  = *(const float4*)(sc + base + i * 4);
        *(float4*)&pv[i * 4] = *(const float4*)(pa + base + i * 4);
    }

    float p[16], l[16];
#pragma unroll
    for (int i = 0; i < 16; i++) {
        float si = s[i];
        float e  = expf(-fabsf(si));
        float den = 1.f + e;
        p[i] = (si >= 0.f) ? (1.f / den) : (e / den);
        l[i] = fmaxf(-(fmaxf(si, 0.f) + log1pf(e)), LOGTINY);
    }

#pragma unroll
    for (int i = 1; i < 16; i++) l[i] += l[i - 1];
    float prefl = block_exscan512(l[15], sh);

    float cp[16];
#pragma unroll
    for (int i = 0; i < 16; i++) {
        cp[i] = expf(prefl + (i ? l[i - 1] : 0.f));
        pv[i] = pv[i] / fmaxf(cp[i], 1e-10f);
    }
#pragma unroll
    for (int i = 1; i < 16; i++) pv[i] += pv[i - 1];
    float prefu = block_exscan512(pv[15], sh);

    float asum = 0.f;
#pragma unroll
    for (int i = 0; i < 16; i++) {
        float al = p[i] * cp[i] * (prefu + pv[i]);
        s[i] = al;
        asum += al;
    }
#pragma unroll
    for (int i = 0; i < 4; i++)
        *(float4*)(out_align + (size_t)b * TT + base + i * 4) = *(float4*)&s[i * 4];

    float prefa = block_exscan512(asum, sh);
    if (tid == 511) g_sumA[b] = prefa + asum;
}

// ---------------- kernel D: partial S = alignment @ value (512 thr, 8-row ILP) ----------------
__global__ __launch_bounds__(512) void ctx_reduce_kernel(
    const float* __restrict__ value, const float* __restrict__ align) {
    __shared__ float ash[256];
    __shared__ float4 red[7][64];
    int tc = blockIdx.x;
    int b  = blockIdx.y;
    int tid = threadIdx.x;
    int k4 = tid & 63, tr = tid >> 6;       // 64 float4 cols x 8 t-offsets
    int t0 = tc * 256;
    if (tid < 256) ash[tid] = align[(size_t)b * TT + t0 + tid];
    __syncthreads();
    const float4* vp = (const float4*)(value + ((size_t)b * TT + t0) * VD);
    float4 acc = make_float4(0.f, 0.f, 0.f, 0.f);
#pragma unroll 8
    for (int t = tr; t < 256; t += 8) {
        float a = ash[t];
        float4 v = vp[(size_t)t * 64 + k4];
        acc.x = fmaf(a, v.x, acc.x);
        acc.y = fmaf(a, v.y, acc.y);
        acc.z = fmaf(a, v.z, acc.z);
        acc.w = fmaf(a, v.w, acc.w);
    }
    if (tr) red[tr - 1][k4] = acc;
    __syncthreads();
    if (tr == 0) {
#pragma unroll
        for (int r = 0; r < 7; r++) {
            float4 rr = red[r][k4];
            acc.x += rr.x; acc.y += rr.y; acc.z += rr.z; acc.w += rr.w;
        }
        *(float4*)&g_Spart[tc][b][k4 * 4] = acc;
    }
}

// ---------------- kernel E: reduce partials + context = S @ Wv + sumA * bv ----------------
__global__ __launch_bounds__(256) void ctx_tail_kernel(
    const float* __restrict__ Wv, const float* __restrict__ bv,
    float* __restrict__ out_ctx) {
    __shared__ float Ssh[VD];
    int b = blockIdx.x;
    int tid = threadIdx.x;                  // 256
    float s = 0.f;
#pragma unroll
    for (int c = 0; c < 32; c++) s += g_Spart[c][b][tid];
    Ssh[tid] = s;
    __syncthreads();
    if (tid < DD) {
        float acc = g_sumA[b] * bv[tid];
#pragma unroll 8
        for (int k = 0; k < VD; k++)
            acc += Ssh[k] * Wv[(size_t)k * DD + tid];
        out_ctx[b * DD + tid] = acc;
    }
}

// ---------------- launcher ----------------
extern "C" void kernel_launch(void* const* d_in, const int* in_sizes, int n_in,
                              void* d_out, int out_size) {
    (void)in_sizes; (void)n_in; (void)out_size;
    const float* query = (const float*)d_in[0];
    const float* value = (const float*)d_in[1];
    const float* prev  = (const float*)d_in[2];
    const float* Wq    = (const float*)d_in[3];
    const float* bq    = (const float*)d_in[4];
    const float* Wv    = (const float*)d_in[5];
    const float* bv    = (const float*)d_in[6];
    const float* av    = (const float*)d_in[7];
    const float* sbias = (const float*)d_in[8];

    float* out       = (float*)d_out;
    float* out_ctx   = out;                  // [32, 128]
    float* out_align = out + BB * DD;        // [32, 8192]

    const int SCORE_DYN = 2 * STAGE_BYTES + 1024;   // two 48KB stages + align pad
    cudaFuncSetAttribute(score_kernel, cudaFuncAttributeMaxDynamicSharedMemorySize, SCORE_DYN);

    qproj_kernel<<<BB, DD>>>(query, Wq, bq);
    wvt_kernel<<<DD, VD>>>(Wv);
    score_kernel<<<dim3(TT / TILE_T, BB), 256, SCORE_DYN>>>(value, Wv, bv, av, sbias);
    scan_kernel<<<BB, 512>>>(prev, out_align);
    ctx_reduce_kernel<<<dim3(32, BB), 512>>>(value, out_align);
    ctx_tail_kernel<<<BB, 256>>>(Wv, bv, out_ctx);
}

// round 9
// speedup vs baseline: 3.2453x; 1.1512x over previous
#include <cuda_runtime.h>
#include <cstdint>
#include <cstddef>

// Problem shapes (fixed)
#define BB   32
#define TT   8192
#define QD   512
#define VD   256
#define DD   128
#define TILE_T 256           // t-rows per score CTA (2 x 128-row MMA accumulators)
#define KCH    32            // k-floats per SMEM chunk (= 128B = one SW128 atom row)
#define NCHUNK (VD / KCH)    // 8
#define STAGE_BYTES (3 * 16384)   // A0 + A1 + B per stage

#if defined(__CUDA_ARCH__) && (defined(__CUDA_ARCH_FEAT_SM103_ALL) || \
                               defined(__CUDA_ARCH_FEAT_SM100_ALL) || \
                               defined(__CUDA_ARCH_SPECIFIC__)     || \
                               defined(__CUDA_ARCH_FAMILY_SPECIFIC__))
#define HAS_TCGEN05 1
#else
#define HAS_TCGEN05 0
#endif

// ---------------- device scratch (no allocation allowed) ----------------
__device__ float g_q[BB * DD];
__device__ float g_WvT[DD * VD];        // Wv transposed: [d][k]
__device__ float g_score[BB * TT];
__device__ __align__(16) float g_Spart[16][BB][VD];
__device__ float g_sumA[BB];

// ---------------- generic PTX helpers ----------------
__device__ __forceinline__ uint32_t smem_u32(const void* p) {
    uint32_t a;
    asm("{ .reg .u64 t; cvta.to.shared.u64 t, %1; cvt.u32.u64 %0, t; }" : "=r"(a) : "l"(p));
    return a;
}
__device__ __forceinline__ uint32_t elect_one_pred() {
    uint32_t p;
    asm volatile("{\n\t.reg .pred p;\n\telect.sync _|p, 0xFFFFFFFF;\n\tselp.b32 %0, 1, 0, p;\n\t}" : "=r"(p));
    return p;
}
__device__ __forceinline__ float tanh_fast(float x) {
    float y;
    asm("tanh.approx.f32 %0, %1;" : "=f"(y) : "f"(x));
    return y;
}

#define MBARRIER_INIT(addr, cnt) \
    asm volatile("mbarrier.init.shared.b64 [%0], %1;" :: "r"(addr), "r"(cnt) : "memory")

#define MBARRIER_WAIT_PARITY(mbar, parity) do {                                   \
    uint32_t _m = (mbar); uint32_t _p = (parity); uint32_t _d;                    \
    asm volatile("{\n\t.reg .pred p;\n\t"                                         \
        "mbarrier.try_wait.parity.acquire.cta.shared::cta.b64 p, [%1], %2;\n\t"   \
        "selp.b32 %0, 1, 0, p;\n\t}" : "=r"(_d) : "r"(_m), "r"(_p) : "memory");   \
    if (!_d) {                                                                    \
        asm volatile("{\n\t.reg .pred P1;\n\t"                                    \
            "WL_%=:\n\t"                                                          \
            "mbarrier.try_wait.parity.acquire.cta.shared::cta.b64 P1, [%0], %1, 0x989680;\n\t" \
            "@P1 bra.uni WD_%=;\n\t"                                              \
            "bra.uni WL_%=;\n\t"                                                  \
            "WD_%=:\n\t}" :: "r"(_m), "r"(_p) : "memory");                        \
    }                                                                             \
} while (0)

// ---------------- tcgen05 helpers ----------------
#define TCGEN05_ALLOC(res_addr, ncols) \
    asm volatile("tcgen05.alloc.cta_group::1.sync.aligned.shared::cta.b32 [%0], %1;" \
                 :: "r"(res_addr), "r"((uint32_t)(ncols)) : "memory")
#define TCGEN05_RELINQ() \
    asm volatile("tcgen05.relinquish_alloc_permit.cta_group::1.sync.aligned;")
#define TCGEN05_DEALLOC(tmem, ncols) \
    asm volatile("tcgen05.dealloc.cta_group::1.sync.aligned.b32 %0, %1;" :: "r"(tmem), "r"((uint32_t)(ncols)))
#define TCGEN05_COMMIT(mbar) \
    asm volatile("tcgen05.commit.cta_group::1.mbarrier::arrive::one.shared::cluster.b64 [%0];" \
                 :: "r"(mbar) : "memory")
#define TCGEN05_FENCE_AFTER() \
    asm volatile("tcgen05.fence::after_thread_sync;" ::: "memory")
#define TCGEN05_WAIT_LD() \
    asm volatile("tcgen05.wait::ld.sync.aligned;" ::: "memory")
#define FENCE_PROXY_ASYNC() \
    asm volatile("fence.proxy.async.shared::cta;" ::: "memory")

#define TCGEN05_LD_X32(r, tmem_addr)                                              \
    asm volatile("tcgen05.ld.sync.aligned.32x32b.x32.b32 "                        \
        "{%0, %1, %2, %3, %4, %5, %6, %7, "                                       \
        " %8, %9, %10, %11, %12, %13, %14, %15, "                                 \
        " %16, %17, %18, %19, %20, %21, %22, %23, "                               \
        " %24, %25, %26, %27, %28, %29, %30, %31}, [%32];"                        \
        : "=r"((r)[0]),  "=r"((r)[1]),  "=r"((r)[2]),  "=r"((r)[3]),              \
          "=r"((r)[4]),  "=r"((r)[5]),  "=r"((r)[6]),  "=r"((r)[7]),              \
          "=r"((r)[8]),  "=r"((r)[9]),  "=r"((r)[10]), "=r"((r)[11]),             \
          "=r"((r)[12]), "=r"((r)[13]), "=r"((r)[14]), "=r"((r)[15]),             \
          "=r"((r)[16]), "=r"((r)[17]), "=r"((r)[18]), "=r"((r)[19]),             \
          "=r"((r)[20]), "=r"((r)[21]), "=r"((r)[22]), "=r"((r)[23]),             \
          "=r"((r)[24]), "=r"((r)[25]), "=r"((r)[26]), "=r"((r)[27]),             \
          "=r"((r)[28]), "=r"((r)[29]), "=r"((r)[30]), "=r"((r)[31])              \
        : "r"(tmem_addr))

// SW128 K-major SMEM descriptor (LBO=1, SBO=64, version=1, layout=SW128)
static __device__ constexpr uint64_t SMEM_DESC_BASE_SW128 =
    (uint64_t(2) << 61) | (uint64_t(1) << 46) | (uint64_t(64) << 32) | (uint64_t(1) << 16);
__device__ __forceinline__ uint64_t make_desc(uint32_t addr) {
    return SMEM_DESC_BASE_SW128 | ((uint64_t)(addr >> 4) & 0x3FFF);
}

#if HAS_TCGEN05
__device__ __forceinline__ void mma_tf32_ss(uint32_t d_tmem, uint64_t a_desc, uint64_t b_desc,
                                            uint32_t idesc, uint32_t enable) {
    asm volatile(
        "{\n\t.reg .pred p;\n\t"
        "setp.ne.u32 p, %4, 0;\n\t"
        "tcgen05.mma.cta_group::1.kind::tf32 [%0], %1, %2, %3, {%5, %5, %5, %5}, p;\n\t}"
        :: "r"(d_tmem), "l"(a_desc), "l"(b_desc), "r"(idesc), "r"(enable), "r"(0u)
        : "memory");
}
#endif

// ---------------- f32x2 packed-FMA helpers (fallback path) ----------------
__device__ __forceinline__ unsigned long long pack2(float lo, float hi) {
    unsigned long long r;
    asm("mov.b64 %0, {%1, %2};" : "=l"(r) : "f"(lo), "f"(hi));
    return r;
}
__device__ __forceinline__ void unpack2(unsigned long long v, float& lo, float& hi) {
    asm("mov.b64 {%0, %1}, %2;" : "=f"(lo), "=f"(hi) : "l"(v));
}
__device__ __forceinline__ void ffma2(unsigned long long& d,
                                      unsigned long long a,
                                      unsigned long long b) {
    asm("fma.rn.f32x2 %0, %1, %2, %0;" : "+l"(d) : "l"(a), "l"(b));
}

// ---------------- kernel A: q = query @ Wq + bq (512 thr, k-split x4) ----------------
__global__ __launch_bounds__(512) void qproj_kernel(const float* __restrict__ query,
                                                    const float* __restrict__ Wq,
                                                    const float* __restrict__ bq) {
    __shared__ float part[4][DD];
    int b  = blockIdx.x;
    int d  = threadIdx.x & 127;
    int sl = threadIdx.x >> 7;           // 4 k-slices of 128
    const float* qr = query + (size_t)b * QD + sl * 128;
    const float* wq = Wq + (size_t)sl * 128 * DD + d;
    float a0 = 0.f, a1 = 0.f, a2 = 0.f, a3 = 0.f;
#pragma unroll 8
    for (int k = 0; k < 128; k += 4) {
        a0 += qr[k + 0] * wq[(size_t)(k + 0) * DD];
        a1 += qr[k + 1] * wq[(size_t)(k + 1) * DD];
        a2 += qr[k + 2] * wq[(size_t)(k + 2) * DD];
        a3 += qr[k + 3] * wq[(size_t)(k + 3) * DD];
    }
    part[sl][d] = (a0 + a1) + (a2 + a3);
    __syncthreads();
    if (sl == 0)
        g_q[b * DD + d] = bq[d] + (part[0][d] + part[1][d]) + (part[2][d] + part[3][d]);
}

// ---------------- kernel A2: coalesced transpose WvT[d][k] = Wv[k][d] ----------------
__global__ void wvt_kernel(const float* __restrict__ Wv) {
    __shared__ float tile[32][33];
    int k0 = blockIdx.x * 32;            // 8 blocks over VD
    int d0 = blockIdx.y * 32;            // 4 blocks over DD
    int tx = threadIdx.x, ty = threadIdx.y;   // (32, 8)
#pragma unroll
    for (int r = 0; r < 4; r++)
        tile[ty + r * 8][tx] = Wv[(size_t)(k0 + ty + r * 8) * DD + d0 + tx];
    __syncthreads();
#pragma unroll
    for (int r = 0; r < 4; r++)
        g_WvT[(size_t)(d0 + ty + r * 8) * VD + k0 + tx] = tile[tx][ty + r * 8];
}

// ---------------- profiling-slot filler (also zeroes g_sumA deterministically) ----------------
__global__ void zero_kernel() {
    if (threadIdx.x < BB) g_sumA[threadIdx.x] = 0.f;
}

// ---------------- kernel B: score GEMM + Bahdanau epilogue ----------------
__global__ __launch_bounds__(256) void score_kernel(
    const float* __restrict__ value,
    const float* __restrict__ Wv,
    const float* __restrict__ bv,
    const float* __restrict__ av,
    const float* __restrict__ sbias) {

#if HAS_TCGEN05
    extern __shared__ char dynraw[];
    __shared__ uint32_t s_tmem[1];
    __shared__ __align__(8) unsigned long long s_mbar[2];
    __shared__ float qsh[DD], avsh[DD];

    char* dbase = (char*)(((uintptr_t)dynraw + 1023) & ~(uintptr_t)1023);

    int tid = threadIdx.x;
    int wid = tid >> 5, lid = tid & 31;
    int b = blockIdx.y, t0 = blockIdx.x * TILE_T;

    uint32_t mbar0 = smem_u32(&s_mbar[0]);
    uint32_t mbar1 = smem_u32(&s_mbar[1]);
    uint32_t tptr_u32 = smem_u32(&s_tmem[0]);

    if (tid < DD) {
        qsh[tid]  = g_q[b * DD + tid] + bv[tid];
        avsh[tid] = av[tid];
    }
    if (tid == 0) {
        MBARRIER_INIT(mbar0, 1);
        MBARRIER_INIT(mbar1, 1);
    }
    if (wid == 0) {
        TCGEN05_ALLOC(tptr_u32, 256);       // D0 @ +0, D1 @ +128
        TCGEN05_RELINQ();
    }
    __syncthreads();
    uint32_t tmem = s_tmem[0];

    const float* vrow = value + ((size_t)b * TT + t0) * VD;
    const float* wrow = g_WvT;

    const uint32_t idesc = (1u << 4) | (2u << 7) | (2u << 10)
                         | ((DD / 8) << 17) | (8u << 24);

    float4 vr[8], wr[4];
    auto load_regs = [&](int c) {
#pragma unroll
        for (int i = 0; i < 8; i++) {        // 2048 float4: 256 value rows x 8
            int j = i * 256 + tid;
            int row = j >> 3;
            int kp  = (j & 7) * 4;
            vr[i] = *(const float4*)(vrow + (size_t)row * VD + c * KCH + kp);
        }
#pragma unroll
        for (int i = 0; i < 4; i++) {        // 1024 float4: 128 WvT rows x 8
            int j = i * 256 + tid;
            int row = j >> 3;
            int kp  = (j & 7) * 4;
            wr[i] = *(const float4*)(wrow + (size_t)row * VD + c * KCH + kp);
        }
    };
    auto store_regs = [&](char* stage) {
        char* a0p = stage;
        char* a1p = stage + 16384;
        char* bp  = stage + 32768;
#pragma unroll
        for (int i = 0; i < 8; i++) {
            int j = i * 256 + tid;
            int row = j >> 3;
            uint32_t off = (row & 127) * 128 + (j & 7) * 16;
            uint32_t sw = off ^ ((off >> 3) & 0x70);
            *(float4*)(((row >> 7) ? a1p : a0p) + sw) = vr[i];
        }
#pragma unroll
        for (int i = 0; i < 4; i++) {
            int j = i * 256 + tid;
            int row = j >> 3;
            uint32_t off = row * 128 + (j & 7) * 16;
            uint32_t sw = off ^ ((off >> 3) & 0x70);
            *(float4*)(bp + sw) = wr[i];
        }
    };

    load_regs(0);
    for (int c = 0; c < NCHUNK; c++) {
        int buf = c & 1;
        uint32_t mb = buf ? mbar1 : mbar0;
        if (c >= 2) MBARRIER_WAIT_PARITY(mb, (uint32_t)(((c >> 1) - 1) & 1));
        char* stage = dbase + buf * STAGE_BYTES;
        store_regs(stage);
        __syncthreads();
        // issue MMAs FIRST so tensor pipe starts before the prefetch LDGs
        if (wid == 0) {
            FENCE_PROXY_ASYNC();
            if (elect_one_pred()) {
                uint64_t a0 = make_desc(smem_u32(stage));
                uint64_t a1 = make_desc(smem_u32(stage + 16384));
                uint64_t b0 = make_desc(smem_u32(stage + 32768));
#pragma unroll
                for (int s = 0; s < 4; s++) {
                    uint32_t en = (uint32_t)((c > 0) || (s > 0));
                    mma_tf32_ss(tmem,        a0 + s * 2, b0 + s * 2, idesc, en);
                    mma_tf32_ss(tmem + 128,  a1 + s * 2, b0 + s * 2, idesc, en);
                }
                TCGEN05_COMMIT(mb);
            }
        }
        if (c + 1 < NCHUNK) load_regs(c + 1);
    }
    MBARRIER_WAIT_PARITY(mbar0, 1u);
    MBARRIER_WAIT_PARITY(mbar1, 1u);

    TCGEN05_FENCE_AFTER();

    // epilogue: warp w -> accumulator part=w>>2, subpartition w&3; LDTM pairs
    int part = wid >> 2;
    float s = 0.f;
#pragma unroll
    for (int gp = 0; gp < 2; gp++) {
        uint32_t dr0[32], dr1[32];
        TCGEN05_LD_X32(dr0, tmem + part * 128 + gp * 64);
        TCGEN05_LD_X32(dr1, tmem + part * 128 + gp * 64 + 32);
        TCGEN05_WAIT_LD();
#pragma unroll
        for (int j = 0; j < 32; j++) {
            int col = gp * 64 + j;
            s += avsh[col] * tanh_fast(qsh[col] + __uint_as_float(dr0[j]));
        }
#pragma unroll
        for (int j = 0; j < 32; j++) {
            int col = gp * 64 + 32 + j;
            s += avsh[col] * tanh_fast(qsh[col] + __uint_as_float(dr1[j]));
        }
    }
    int trow = part * 128 + (wid & 3) * 32 + lid;
    g_score[(size_t)b * TT + t0 + trow] = s + sbias[0];

    __syncthreads();
    if (wid == 0) TCGEN05_DEALLOC(tmem, 256);
    (void)Wv;

#else
    // ======== FFMA2 fallback (non-"a" compilation pass): two 128-row halves ====
    __shared__ __align__(16) float bsh[16][DD];
    __shared__ float vsh[16][128 + 1];

    int b  = blockIdx.y;
    int tid = threadIdx.x;
    int tx = tid & 15;
    int ty = tid >> 4;

    for (int half = 0; half < 2; half++) {
        int t0 = blockIdx.x * TILE_T + half * 128;

        unsigned long long acc[8][4];
#pragma unroll
        for (int i = 0; i < 8; i++)
#pragma unroll
            for (int j = 0; j < 4; j++) acc[i][j] = 0ull;

        const float* vptr = value + ((size_t)b * TT + t0) * VD;

        for (int kc = 0; kc < VD; kc += 16) {
            __syncthreads();
#pragma unroll
            for (int r = 0; r < 2; r++) {
                int idx = tid + r * 256;
                int row = idx >> 2;
                int k4  = (idx & 3) * 4;
                float4 vv = *(const float4*)(vptr + (size_t)row * VD + kc + k4);
                vsh[k4 + 0][row] = vv.x;
                vsh[k4 + 1][row] = vv.y;
                vsh[k4 + 2][row] = vv.z;
                vsh[k4 + 3][row] = vv.w;
            }
#pragma unroll
            for (int r = 0; r < 2; r++) {
                int idx = tid + r * 256;
                int kk  = idx >> 5;
                int d4  = (idx & 31) * 4;
                *(float4*)&bsh[kk][d4] = *(const float4*)(Wv + (size_t)(kc + kk) * DD + d4);
            }
            __syncthreads();

#pragma unroll
            for (int kk = 0; kk < 16; kk++) {
                unsigned long long ap[8];
#pragma unroll
                for (int i = 0; i < 8; i++) {
                    float a = vsh[kk][ty * 8 + i];
                    ap[i] = pack2(a, a);
                }
                unsigned long long bp[4];
#pragma unroll
                for (int j = 0; j < 4; j++)
                    bp[j] = *(const unsigned long long*)&bsh[kk][tx * 8 + j * 2];
#pragma unroll
                for (int i = 0; i < 8; i++)
#pragma unroll
                    for (int j = 0; j < 4; j++)
                        ffma2(acc[i][j], ap[i], bp[j]);
            }
        }

        float qv[8], avv[8];
#pragma unroll
        for (int j = 0; j < 8; j++) {
            int c = tx * 8 + j;
            qv[j]  = g_q[b * DD + c] + bv[c];
            avv[j] = av[c];
        }
        float part[8];
#pragma unroll
        for (int i = 0; i < 8; i++) {
            float s = 0.f;
#pragma unroll
            for (int j = 0; j < 4; j++) {
                float lo, hi;
                unpack2(acc[i][j], lo, hi);
                s += avv[2 * j]     * tanh_fast(qv[2 * j]     + lo);
                s += avv[2 * j + 1] * tanh_fast(qv[2 * j + 1] + hi);
            }
            part[i] = s;
        }
#pragma unroll
        for (int o = 8; o >= 1; o >>= 1)
#pragma unroll
            for (int i = 0; i < 8; i++)
                part[i] += __shfl_down_sync(0xffffffffu, part[i], o, 16);

        if (tx == 0) {
            float bias = *sbias;
#pragma unroll
            for (int i = 0; i < 8; i++)
                g_score[b * TT + t0 + ty * 8 + i] = part[i] + bias;
        }
        __syncthreads();
    }
#endif
}

// ---------------- kernel C: monotonic-attention scan ----------------
__device__ __forceinline__ float block_exscan512(float tsum, float* sh) {
    int lane = threadIdx.x & 31, wid = threadIdx.x >> 5;
    float x = tsum;
#pragma unroll
    for (int o = 1; o < 32; o <<= 1) {
        float y = __shfl_up_sync(0xffffffffu, x, o);
        if (lane >= o) x += y;
    }
    __syncthreads();
    if (lane == 31) sh[wid] = x;
    __syncthreads();
    if (wid == 0) {
        float v = (lane < 16) ? sh[lane] : 0.f;
        float xx = v;
#pragma unroll
        for (int o = 1; o < 32; o <<= 1) {
            float y = __shfl_up_sync(0xffffffffu, xx, o);
            if (lane >= o) xx += y;
        }
        if (lane < 16) sh[lane] = xx - v;
    }
    __syncthreads();
    return sh[wid] + (x - tsum);
}

__global__ __launch_bounds__(512) void scan_kernel(
    const float* __restrict__ prev, float* __restrict__ out_align) {
    __shared__ float sh[32];
    const float LOGTINY = -87.336544f;
    int b = blockIdx.x;
    int tid = threadIdx.x;
    int base = tid * 16;
    const float* sc = g_score + (size_t)b * TT;
    const float* pa = prev + (size_t)b * TT;

    float s[16], pv[16];
#pragma unroll
    for (int i = 0; i < 4; i++) {
        *(float4*)&s[i * 4]  = *(const float4*)(sc + base + i * 4);
        *(float4*)&pv[i * 4] = *(const float4*)(pa + base + i * 4);
    }

    float p[16], l[16];
#pragma unroll
    for (int i = 0; i < 16; i++) {
        float si = s[i];
        float e  = expf(-fabsf(si));
        float den = 1.f + e;
        p[i] = (si >= 0.f) ? (1.f / den) : (e / den);
        l[i] = fmaxf(-(fmaxf(si, 0.f) + log1pf(e)), LOGTINY);
    }

#pragma unroll
    for (int i = 1; i < 16; i++) l[i] += l[i - 1];
    float prefl = block_exscan512(l[15], sh);

    float cp[16];
#pragma unroll
    for (int i = 0; i < 16; i++) {
        cp[i] = expf(prefl + (i ? l[i - 1] : 0.f));
        pv[i] = pv[i] / fmaxf(cp[i], 1e-10f);
    }
#pragma unroll
    for (int i = 1; i < 16; i++) pv[i] += pv[i - 1];
    float prefu = block_exscan512(pv[15], sh);

    float asum = 0.f;
#pragma unroll
    for (int i = 0; i < 16; i++) {
        float al = p[i] * cp[i] * (prefu + pv[i]);
        s[i] = al;
        asum += al;
    }
#pragma unroll
    for (int i = 0; i < 4; i++)
        *(float4*)(out_align + (size_t)b * TT + base + i * 4) = *(float4*)&s[i * 4];

    float prefa = block_exscan512(asum, sh);
    if (tid == 511) g_sumA[b] = prefa + asum;
}

// ---------------- kernel D: partial S = alignment @ value (512 t-rows/block) ----------------
__global__ __launch_bounds__(512) void ctx_reduce_kernel(
    const float* __restrict__ value, const float* __restrict__ align) {
    __shared__ float ash[512];
    __shared__ float4 red[7][64];
    int tc = blockIdx.x;                    // 16 chunks of 512 t
    int b  = blockIdx.y;
    int tid = threadIdx.x;
    int k4 = tid & 63, tr = tid >> 6;       // 64 float4 cols x 8 t-offsets
    int t0 = tc * 512;
    ash[tid] = align[(size_t)b * TT + t0 + tid];
    __syncthreads();
    const float4* vp = (const float4*)(value + ((size_t)b * TT + t0) * VD);
    float4 acc = make_float4(0.f, 0.f, 0.f, 0.f);
#pragma unroll 8
    for (int t = tr; t < 512; t += 8) {
        float a = ash[t];
        float4 v = vp[(size_t)t * 64 + k4];
        acc.x = fmaf(a, v.x, acc.x);
        acc.y = fmaf(a, v.y, acc.y);
        acc.z = fmaf(a, v.z, acc.z);
        acc.w = fmaf(a, v.w, acc.w);
    }
    if (tr) red[tr - 1][k4] = acc;
    __syncthreads();
    if (tr == 0) {
#pragma unroll
        for (int r = 0; r < 7; r++) {
            float4 rr = red[r][k4];
            acc.x += rr.x; acc.y += rr.y; acc.z += rr.z; acc.w += rr.w;
        }
        *(float4*)&g_Spart[tc][b][k4 * 4] = acc;
    }
}

// ---------------- kernel E: reduce partials + context = S @ Wv + sumA * bv ----------------
__global__ __launch_bounds__(256) void ctx_tail_kernel(
    const float* __restrict__ Wv, const float* __restrict__ bv,
    float* __restrict__ out_ctx) {
    __shared__ float Ssh[VD];
    __shared__ float half1[DD];
    int b = blockIdx.x;
    int tid = threadIdx.x;                  // 256
    float s = 0.f;
#pragma unroll
    for (int c = 0; c < 16; c++) s += g_Spart[c][b][tid];
    Ssh[tid] = s;
    __syncthreads();
    int d = tid & 127, hf = tid >> 7;       // k-split x2
    float acc = 0.f;
    const float* wv = Wv + (size_t)hf * 128 * DD + d;
#pragma unroll 8
    for (int k = 0; k < 128; k++)
        acc += Ssh[hf * 128 + k] * wv[(size_t)k * DD];
    if (hf) half1[d] = acc;
    __syncthreads();
    if (hf == 0)
        out_ctx[b * DD + d] = acc + half1[d] + g_sumA[b] * bv[d];
}

// ---------------- launcher ----------------
extern "C" void kernel_launch(void* const* d_in, const int* in_sizes, int n_in,
                              void* d_out, int out_size) {
    (void)in_sizes; (void)n_in; (void)out_size;
    const float* query = (const float*)d_in[0];
    const float* value = (const float*)d_in[1];
    const float* prev  = (const float*)d_in[2];
    const float* Wq    = (const float*)d_in[3];
    const float* bq    = (const float*)d_in[4];
    const float* Wv    = (const float*)d_in[5];
    const float* bv    = (const float*)d_in[6];
    const float* av    = (const float*)d_in[7];
    const float* sbias = (const float*)d_in[8];

    float* out       = (float*)d_out;
    float* out_ctx   = out;                  // [32, 128]
    float* out_align = out + BB * DD;        // [32, 8192]

    const int SCORE_DYN = 2 * STAGE_BYTES + 1024;
    cudaFuncSetAttribute(score_kernel, cudaFuncAttributeMaxDynamicSharedMemorySize, SCORE_DYN);

    qproj_kernel<<<BB, 512>>>(query, Wq, bq);                 // launch 0
    wvt_kernel<<<dim3(VD / 32, DD / 32), dim3(32, 8)>>>(Wv);  // launch 1
    zero_kernel<<<1, 32>>>();                                 // launch 2 (prof slot filler)
    score_kernel<<<dim3(TT / TILE_T, BB), 256, SCORE_DYN>>>(value, Wv, bv, av, sbias); // launch 3 -> ncu
    scan_kernel<<<BB, 512>>>(prev, out_align);
    ctx_reduce_kernel<<<dim3(16, BB), 512>>>(value, out_align);
    ctx_tail_kernel<<<BB, 256>>>(Wv, bv, out_ctx);
}

// round 10
// speedup vs baseline: 4.0039x; 1.2338x over previous
#include <cuda_runtime.h>
#include <cstdint>
#include <cstddef>

// Problem shapes (fixed)
#define BB   32
#define TT   8192
#define QD   512
#define VD   256
#define DD   128
#define TILE_T 256           // t-rows per score CTA (2 x 128-row MMA accumulators)
#define KCH    32            // k-floats per SMEM chunk (= 128B = one SW128 atom row)
#define NCHUNK (VD / KCH)    // 8
#define STAGE_BYTES (3 * 16384)   // A0 + A1 + B per stage

#if defined(__CUDA_ARCH__) && (defined(__CUDA_ARCH_FEAT_SM103_ALL) || \
                               defined(__CUDA_ARCH_FEAT_SM100_ALL) || \
                               defined(__CUDA_ARCH_SPECIFIC__)     || \
                               defined(__CUDA_ARCH_FAMILY_SPECIFIC__))
#define HAS_TCGEN05 1
#else
#define HAS_TCGEN05 0
#endif

// ---------------- device scratch (no allocation allowed) ----------------
__device__ float g_q[BB * DD];
__device__ float g_WvT[DD * VD];        // Wv transposed: [d][k]
__device__ float g_score[BB * TT];
__device__ __align__(16) float g_Spart[16][BB][VD];
__device__ float g_sumA[BB];

// ---------------- generic PTX helpers ----------------
__device__ __forceinline__ uint32_t smem_u32(const void* p) {
    uint32_t a;
    asm("{ .reg .u64 t; cvta.to.shared.u64 t, %1; cvt.u32.u64 %0, t; }" : "=r"(a) : "l"(p));
    return a;
}
__device__ __forceinline__ uint32_t elect_one_pred() {
    uint32_t p;
    asm volatile("{\n\t.reg .pred p;\n\telect.sync _|p, 0xFFFFFFFF;\n\tselp.b32 %0, 1, 0, p;\n\t}" : "=r"(p));
    return p;
}
__device__ __forceinline__ float tanh_fast(float x) {
    float y;
    asm("tanh.approx.f32 %0, %1;" : "=f"(y) : "f"(x));
    return y;
}

#define CP_ASYNC16(dst_u32, src_ptr) \
    asm volatile("cp.async.cg.shared.global [%0], [%1], 16;" \
                 :: "r"(dst_u32), "l"(src_ptr) : "memory")
#define CP_ASYNC_COMMIT() asm volatile("cp.async.commit_group;" ::: "memory")
#define CP_ASYNC_WAIT(n)  asm volatile("cp.async.wait_group %0;" :: "n"(n) : "memory")

#define MBARRIER_INIT(addr, cnt) \
    asm volatile("mbarrier.init.shared.b64 [%0], %1;" :: "r"(addr), "r"(cnt) : "memory")

#define MBARRIER_WAIT_PARITY(mbar, parity) do {                                   \
    uint32_t _m = (mbar); uint32_t _p = (parity); uint32_t _d;                    \
    asm volatile("{\n\t.reg .pred p;\n\t"                                         \
        "mbarrier.try_wait.parity.acquire.cta.shared::cta.b64 p, [%1], %2;\n\t"   \
        "selp.b32 %0, 1, 0, p;\n\t}" : "=r"(_d) : "r"(_m), "r"(_p) : "memory");   \
    if (!_d) {                                                                    \
        asm volatile("{\n\t.reg .pred P1;\n\t"                                    \
            "WL_%=:\n\t"                                                          \
            "mbarrier.try_wait.parity.acquire.cta.shared::cta.b64 P1, [%0], %1, 0x989680;\n\t" \
            "@P1 bra.uni WD_%=;\n\t"                                              \
            "bra.uni WL_%=;\n\t"                                                  \
            "WD_%=:\n\t}" :: "r"(_m), "r"(_p) : "memory");                        \
    }                                                                             \
} while (0)

// ---------------- tcgen05 helpers ----------------
#define TCGEN05_ALLOC(res_addr, ncols) \
    asm volatile("tcgen05.alloc.cta_group::1.sync.aligned.shared::cta.b32 [%0], %1;" \
                 :: "r"(res_addr), "r"((uint32_t)(ncols)) : "memory")
#define TCGEN05_RELINQ() \
    asm volatile("tcgen05.relinquish_alloc_permit.cta_group::1.sync.aligned;")
#define TCGEN05_DEALLOC(tmem, ncols) \
    asm volatile("tcgen05.dealloc.cta_group::1.sync.aligned.b32 %0, %1;" :: "r"(tmem), "r"((uint32_t)(ncols)))
#define TCGEN05_COMMIT(mbar) \
    asm volatile("tcgen05.commit.cta_group::1.mbarrier::arrive::one.shared::cluster.b64 [%0];" \
                 :: "r"(mbar) : "memory")
#define TCGEN05_FENCE_AFTER() \
    asm volatile("tcgen05.fence::after_thread_sync;" ::: "memory")
#define TCGEN05_WAIT_LD() \
    asm volatile("tcgen05.wait::ld.sync.aligned;" ::: "memory")
#define FENCE_PROXY_ASYNC() \
    asm volatile("fence.proxy.async.shared::cta;" ::: "memory")

#define TCGEN05_LD_X32(r, tmem_addr)                                              \
    asm volatile("tcgen05.ld.sync.aligned.32x32b.x32.b32 "                        \
        "{%0, %1, %2, %3, %4, %5, %6, %7, "                                       \
        " %8, %9, %10, %11, %12, %13, %14, %15, "                                 \
        " %16, %17, %18, %19, %20, %21, %22, %23, "                               \
        " %24, %25, %26, %27, %28, %29, %30, %31}, [%32];"                        \
        : "=r"((r)[0]),  "=r"((r)[1]),  "=r"((r)[2]),  "=r"((r)[3]),              \
          "=r"((r)[4]),  "=r"((r)[5]),  "=r"((r)[6]),  "=r"((r)[7]),              \
          "=r"((r)[8]),  "=r"((r)[9]),  "=r"((r)[10]), "=r"((r)[11]),             \
          "=r"((r)[12]), "=r"((r)[13]), "=r"((r)[14]), "=r"((r)[15]),             \
          "=r"((r)[16]), "=r"((r)[17]), "=r"((r)[18]), "=r"((r)[19]),             \
          "=r"((r)[20]), "=r"((r)[21]), "=r"((r)[22]), "=r"((r)[23]),             \
          "=r"((r)[24]), "=r"((r)[25]), "=r"((r)[26]), "=r"((r)[27]),             \
          "=r"((r)[28]), "=r"((r)[29]), "=r"((r)[30]), "=r"((r)[31])              \
        : "r"(tmem_addr))

// SW128 K-major SMEM descriptor (LBO=1, SBO=64, version=1, layout=SW128)
static __device__ constexpr uint64_t SMEM_DESC_BASE_SW128 =
    (uint64_t(2) << 61) | (uint64_t(1) << 46) | (uint64_t(64) << 32) | (uint64_t(1) << 16);
__device__ __forceinline__ uint64_t make_desc(uint32_t addr) {
    return SMEM_DESC_BASE_SW128 | ((uint64_t)(addr >> 4) & 0x3FFF);
}

#if HAS_TCGEN05
__device__ __forceinline__ void mma_tf32_ss(uint32_t d_tmem, uint64_t a_desc, uint64_t b_desc,
                                            uint32_t idesc, uint32_t enable) {
    asm volatile(
        "{\n\t.reg .pred p;\n\t"
        "setp.ne.u32 p, %4, 0;\n\t"
        "tcgen05.mma.cta_group::1.kind::tf32 [%0], %1, %2, %3, {%5, %5, %5, %5}, p;\n\t}"
        :: "r"(d_tmem), "l"(a_desc), "l"(b_desc), "r"(idesc), "r"(enable), "r"(0u)
        : "memory");
}
#endif

// ---------------- f32x2 packed-FMA helpers (fallback path) ----------------
__device__ __forceinline__ unsigned long long pack2(float lo, float hi) {
    unsigned long long r;
    asm("mov.b64 %0, {%1, %2};" : "=l"(r) : "f"(lo), "f"(hi));
    return r;
}
__device__ __forceinline__ void unpack2(unsigned long long v, float& lo, float& hi) {
    asm("mov.b64 {%0, %1}, %2;" : "=f"(lo), "=f"(hi) : "l"(v));
}
__device__ __forceinline__ void ffma2(unsigned long long& d,
                                      unsigned long long a,
                                      unsigned long long b) {
    asm("fma.rn.f32x2 %0, %1, %2, %0;" : "+l"(d) : "l"(a), "l"(b));
}

// ---------------- kernel A: q = query @ Wq + bq (512 thr, k-split x4) ----------------
__global__ __launch_bounds__(512) void qproj_kernel(const float* __restrict__ query,
                                                    const float* __restrict__ Wq,
                                                    const float* __restrict__ bq) {
    __shared__ float part[4][DD];
    int b  = blockIdx.x;
    int d  = threadIdx.x & 127;
    int sl = threadIdx.x >> 7;
    const float* qr = query + (size_t)b * QD + sl * 128;
    const float* wq = Wq + (size_t)sl * 128 * DD + d;
    float a0 = 0.f, a1 = 0.f, a2 = 0.f, a3 = 0.f;
#pragma unroll 8
    for (int k = 0; k < 128; k += 4) {
        a0 += qr[k + 0] * wq[(size_t)(k + 0) * DD];
        a1 += qr[k + 1] * wq[(size_t)(k + 1) * DD];
        a2 += qr[k + 2] * wq[(size_t)(k + 2) * DD];
        a3 += qr[k + 3] * wq[(size_t)(k + 3) * DD];
    }
    part[sl][d] = (a0 + a1) + (a2 + a3);
    __syncthreads();
    if (sl == 0)
        g_q[b * DD + d] = bq[d] + (part[0][d] + part[1][d]) + (part[2][d] + part[3][d]);
}

// ---------------- kernel A2: coalesced transpose WvT[d][k] = Wv[k][d] ----------------
__global__ void wvt_kernel(const float* __restrict__ Wv) {
    __shared__ float tile[32][33];
    int k0 = blockIdx.x * 32;
    int d0 = blockIdx.y * 32;
    int tx = threadIdx.x, ty = threadIdx.y;
#pragma unroll
    for (int r = 0; r < 4; r++)
        tile[ty + r * 8][tx] = Wv[(size_t)(k0 + ty + r * 8) * DD + d0 + tx];
    __syncthreads();
#pragma unroll
    for (int r = 0; r < 4; r++)
        g_WvT[(size_t)(d0 + ty + r * 8) * VD + k0 + tx] = tile[tx][ty + r * 8];
}

// ---------------- profiling-slot filler (also zeroes g_sumA deterministically) ----------------
__global__ void zero_kernel() {
    if (threadIdx.x < BB) g_sumA[threadIdx.x] = 0.f;
}

// ---------------- kernel B: score GEMM + Bahdanau epilogue ----------------
__global__ __launch_bounds__(256) void score_kernel(
    const float* __restrict__ value,
    const float* __restrict__ Wv,
    const float* __restrict__ bv,
    const float* __restrict__ av,
    const float* __restrict__ sbias) {

#if HAS_TCGEN05
    extern __shared__ char dynraw[];
    __shared__ uint32_t s_tmem[1];
    __shared__ __align__(8) unsigned long long s_mbar[2];
    __shared__ float qsh[DD], avsh[DD];

    char* dbase = (char*)(((uintptr_t)dynraw + 1023) & ~(uintptr_t)1023);

    int tid = threadIdx.x;
    int wid = tid >> 5, lid = tid & 31;
    int b = blockIdx.y, t0 = blockIdx.x * TILE_T;

    uint32_t mbar0 = smem_u32(&s_mbar[0]);
    uint32_t mbar1 = smem_u32(&s_mbar[1]);
    uint32_t tptr_u32 = smem_u32(&s_tmem[0]);
    uint32_t stage_u32[2] = { smem_u32(dbase), smem_u32(dbase + STAGE_BYTES) };

    const float* vrow = value + ((size_t)b * TT + t0) * VD;
    const float* wrow = g_WvT;

    // Per-thread copy slots: 8 A-slots (value rows 0..255) + 4 B-slots (WvT rows 0..127).
    // Destination swizzled offsets are chunk-independent; sources advance 128B per chunk.
    uint32_t adst[8], bdst[4];
    const float* asrc[8];
    const float* bsrc[4];
#pragma unroll
    for (int i = 0; i < 8; i++) {
        int j = i * 256 + tid;
        int row = j >> 3;
        uint32_t off = (row & 127) * 128 + (j & 7) * 16;
        uint32_t sw = off ^ ((off >> 3) & 0x70);
        adst[i] = ((row >> 7) ? 16384u : 0u) + sw;
        asrc[i] = vrow + (size_t)row * VD + (j & 7) * 4;
    }
#pragma unroll
    for (int i = 0; i < 4; i++) {
        int j = i * 256 + tid;
        int row = j >> 3;
        uint32_t off = row * 128 + (j & 7) * 16;
        uint32_t sw = off ^ ((off >> 3) & 0x70);
        bdst[i] = 32768u + sw;
        bsrc[i] = wrow + (size_t)row * VD + (j & 7) * 4;
    }

    auto issue_copies = [&](int c, uint32_t sbase) {
#pragma unroll
        for (int i = 0; i < 8; i++)
            CP_ASYNC16(sbase + adst[i], asrc[i] + c * KCH);
#pragma unroll
        for (int i = 0; i < 4; i++)
            CP_ASYNC16(sbase + bdst[i], bsrc[i] + c * KCH);
        CP_ASYNC_COMMIT();
    };

    // start the first two chunk copies immediately
    issue_copies(0, stage_u32[0]);
    issue_copies(1, stage_u32[1]);

    if (tid < DD) {
        qsh[tid]  = g_q[b * DD + tid] + bv[tid];
        avsh[tid] = av[tid];
    }
    if (tid == 0) {
        MBARRIER_INIT(mbar0, 1);
        MBARRIER_INIT(mbar1, 1);
    }
    if (wid == 0) {
        TCGEN05_ALLOC(tptr_u32, 256);       // D0 @ +0, D1 @ +128
        TCGEN05_RELINQ();
    }
    __syncthreads();
    uint32_t tmem = s_tmem[0];

    const uint32_t idesc = (1u << 4) | (2u << 7) | (2u << 10)
                         | ((DD / 8) << 17) | (8u << 24);

    for (int c = 0; c < NCHUNK; c++) {
        int buf = c & 1;
        uint32_t mb = buf ? mbar1 : mbar0;
        uint32_t sbase = stage_u32[buf];
        // retire group for chunk c (pending set ⊆ {G_c, G_{c+1}})
        if (c == NCHUNK - 1) CP_ASYNC_WAIT(0); else CP_ASYNC_WAIT(1);
        __syncthreads();
        if (wid == 0) {
            FENCE_PROXY_ASYNC();
            if (elect_one_pred()) {
                uint64_t a0 = make_desc(sbase);
                uint64_t a1 = make_desc(sbase + 16384);
                uint64_t b0 = make_desc(sbase + 32768);
#pragma unroll
                for (int s = 0; s < 4; s++) {
                    uint32_t en = (uint32_t)((c > 0) || (s > 0));
                    mma_tf32_ss(tmem,        a0 + s * 2, b0 + s * 2, idesc, en);
                    mma_tf32_ss(tmem + 128,  a1 + s * 2, b0 + s * 2, idesc, en);
                }
                TCGEN05_COMMIT(mb);          // phase c>>1 on mbar[buf]
            }
        }
        if (c + 2 < NCHUNK) {
            // wait MMA(c) complete (ordered parity 0,1,0,.. per barrier), then refill
            MBARRIER_WAIT_PARITY(mb, (uint32_t)((c >> 1) & 1));
            issue_copies(c + 2, sbase);
        }
    }
    // drain: final commits are phase 3 (parity 1) on each barrier
    MBARRIER_WAIT_PARITY(mbar0, 1u);
    MBARRIER_WAIT_PARITY(mbar1, 1u);

    TCGEN05_FENCE_AFTER();

    // epilogue: warp w -> accumulator part=w>>2, subpartition w&3; LDTM pairs
    int part = wid >> 2;
    float s = 0.f;
#pragma unroll
    for (int gp = 0; gp < 2; gp++) {
        uint32_t dr0[32], dr1[32];
        TCGEN05_LD_X32(dr0, tmem + part * 128 + gp * 64);
        TCGEN05_LD_X32(dr1, tmem + part * 128 + gp * 64 + 32);
        TCGEN05_WAIT_LD();
#pragma unroll
        for (int j = 0; j < 32; j++) {
            int col = gp * 64 + j;
            s += avsh[col] * tanh_fast(qsh[col] + __uint_as_float(dr0[j]));
        }
#pragma unroll
        for (int j = 0; j < 32; j++) {
            int col = gp * 64 + 32 + j;
            s += avsh[col] * tanh_fast(qsh[col] + __uint_as_float(dr1[j]));
        }
    }
    int trow = part * 128 + (wid & 3) * 32 + lid;
    g_score[(size_t)b * TT + t0 + trow] = s + sbias[0];

    __syncthreads();
    if (wid == 0) TCGEN05_DEALLOC(tmem, 256);
    (void)Wv;

#else
    // ======== FFMA2 fallback (non-"a" compilation pass): two 128-row halves ====
    __shared__ __align__(16) float bsh[16][DD];
    __shared__ float vsh[16][128 + 1];

    int b  = blockIdx.y;
    int tid = threadIdx.x;
    int tx = tid & 15;
    int ty = tid >> 4;

    for (int half = 0; half < 2; half++) {
        int t0 = blockIdx.x * TILE_T + half * 128;

        unsigned long long acc[8][4];
#pragma unroll
        for (int i = 0; i < 8; i++)
#pragma unroll
            for (int j = 0; j < 4; j++) acc[i][j] = 0ull;

        const float* vptr = value + ((size_t)b * TT + t0) * VD;

        for (int kc = 0; kc < VD; kc += 16) {
            __syncthreads();
#pragma unroll
            for (int r = 0; r < 2; r++) {
                int idx = tid + r * 256;
                int row = idx >> 2;
                int k4  = (idx & 3) * 4;
                float4 vv = *(const float4*)(vptr + (size_t)row * VD + kc + k4);
                vsh[k4 + 0][row] = vv.x;
                vsh[k4 + 1][row] = vv.y;
                vsh[k4 + 2][row] = vv.z;
                vsh[k4 + 3][row] = vv.w;
            }
#pragma unroll
            for (int r = 0; r < 2; r++) {
                int idx = tid + r * 256;
                int kk  = idx >> 5;
                int d4  = (idx & 31) * 4;
                *(float4*)&bsh[kk][d4] = *(const float4*)(Wv + (size_t)(kc + kk) * DD + d4);
            }
            __syncthreads();

#pragma unroll
            for (int kk = 0; kk < 16; kk++) {
                unsigned long long ap[8];
#pragma unroll
                for (int i = 0; i < 8; i++) {
                    float a = vsh[kk][ty * 8 + i];
                    ap[i] = pack2(a, a);
                }
                unsigned long long bp[4];
#pragma unroll
                for (int j = 0; j < 4; j++)
                    bp[j] = *(const unsigned long long*)&bsh[kk][tx * 8 + j * 2];
#pragma unroll
                for (int i = 0; i < 8; i++)
#pragma unroll
                    for (int j = 0; j < 4; j++)
                        ffma2(acc[i][j], ap[i], bp[j]);
            }
        }

        float qv[8], avv[8];
#pragma unroll
        for (int j = 0; j < 8; j++) {
            int c = tx * 8 + j;
            qv[j]  = g_q[b * DD + c] + bv[c];
            avv[j] = av[c];
        }
        float part[8];
#pragma unroll
        for (int i = 0; i < 8; i++) {
            float s = 0.f;
#pragma unroll
            for (int j = 0; j < 4; j++) {
                float lo, hi;
                unpack2(acc[i][j], lo, hi);
                s += avv[2 * j]     * tanh_fast(qv[2 * j]     + lo);
                s += avv[2 * j + 1] * tanh_fast(qv[2 * j + 1] + hi);
            }
            part[i] = s;
        }
#pragma unroll
        for (int o = 8; o >= 1; o >>= 1)
#pragma unroll
            for (int i = 0; i < 8; i++)
                part[i] += __shfl_down_sync(0xffffffffu, part[i], o, 16);

        if (tx == 0) {
            float bias = *sbias;
#pragma unroll
            for (int i = 0; i < 8; i++)
                g_score[b * TT + t0 + ty * 8 + i] = part[i] + bias;
        }
        __syncthreads();
    }
#endif
}

// ---------------- kernel C: monotonic-attention scan ----------------
__device__ __forceinline__ float block_exscan512(float tsum, float* sh) {
    int lane = threadIdx.x & 31, wid = threadIdx.x >> 5;
    float x = tsum;
#pragma unroll
    for (int o = 1; o < 32; o <<= 1) {
        float y = __shfl_up_sync(0xffffffffu, x, o);
        if (lane >= o) x += y;
    }
    __syncthreads();
    if (lane == 31) sh[wid] = x;
    __syncthreads();
    if (wid == 0) {
        float v = (lane < 16) ? sh[lane] : 0.f;
        float xx = v;
#pragma unroll
        for (int o = 1; o < 32; o <<= 1) {
            float y = __shfl_up_sync(0xffffffffu, xx, o);
            if (lane >= o) xx += y;
        }
        if (lane < 16) sh[lane] = xx - v;
    }
    __syncthreads();
    return sh[wid] + (x - tsum);
}

__global__ __launch_bounds__(512) void scan_kernel(
    const float* __restrict__ prev, float* __restrict__ out_align) {
    __shared__ float sh[32];
    const float LOGTINY = -87.336544f;
    int b = blockIdx.x;
    int tid = threadIdx.x;
    int base = tid * 16;
    const float* sc = g_score + (size_t)b * TT;
    const float* pa = prev + (size_t)b * TT;

    float s[16], pv[16];
#pragma unroll
    for (int i = 0; i < 4; i++) {
        *(float4*)&s[i * 4]  = *(const float4*)(sc + base + i * 4);
        *(float4*)&pv[i * 4] = *(const float4*)(pa + base + i * 4);
    }

    float p[16], l[16];
#pragma unroll
    for (int i = 0; i < 16; i++) {
        float si = s[i];
        float e  = expf(-fabsf(si));
        float den = 1.f + e;
        p[i] = (si >= 0.f) ? (1.f / den) : (e / den);
        l[i] = fmaxf(-(fmaxf(si, 0.f) + log1pf(e)), LOGTINY);
    }

#pragma unroll
    for (int i = 1; i < 16; i++) l[i] += l[i - 1];
    float prefl = block_exscan512(l[15], sh);

    float cp[16];
#pragma unroll
    for (int i = 0; i < 16; i++) {
        cp[i] = expf(prefl + (i ? l[i - 1] : 0.f));
        pv[i] = pv[i] / fmaxf(cp[i], 1e-10f);
    }
#pragma unroll
    for (int i = 1; i < 16; i++) pv[i] += pv[i - 1];
    float prefu = block_exscan512(pv[15], sh);

    float asum = 0.f;
#pragma unroll
    for (int i = 0; i < 16; i++) {
        float al = p[i] * cp[i] * (prefu + pv[i]);
        s[i] = al;
        asum += al;
    }
#pragma unroll
    for (int i = 0; i < 4; i++)
        *(float4*)(out_align + (size_t)b * TT + base + i * 4) = *(float4*)&s[i * 4];

    float prefa = block_exscan512(asum, sh);
    if (tid == 511) g_sumA[b] = prefa + asum;
}

// ---------------- kernel D: partial S = alignment @ value (512 t-rows/block) ----------------
__global__ __launch_bounds__(512) void ctx_reduce_kernel(
    const float* __restrict__ value, const float* __restrict__ align) {
    __shared__ float ash[512];
    __shared__ float4 red[7][64];
    int tc = blockIdx.x;
    int b  = blockIdx.y;
    int tid = threadIdx.x;
    int k4 = tid & 63, tr = tid >> 6;
    int t0 = tc * 512;
    ash[tid] = align[(size_t)b * TT + t0 + tid];
    __syncthreads();
    const float4* vp = (const float4*)(value + ((size_t)b * TT + t0) * VD);
    float4 acc = make_float4(0.f, 0.f, 0.f, 0.f);
#pragma unroll 8
    for (int t = tr; t < 512; t += 8) {
        float a = ash[t];
        float4 v = vp[(size_t)t * 64 + k4];
        acc.x = fmaf(a, v.x, acc.x);
        acc.y = fmaf(a, v.y, acc.y);
        acc.z = fmaf(a, v.z, acc.z);
        acc.w = fmaf(a, v.w, acc.w);
    }
    if (tr) red[tr - 1][k4] = acc;
    __syncthreads();
    if (tr == 0) {
#pragma unroll
        for (int r = 0; r < 7; r++) {
            float4 rr = red[r][k4];
            acc.x += rr.x; acc.y += rr.y; acc.z += rr.z; acc.w += rr.w;
        }
        *(float4*)&g_Spart[tc][b][k4 * 4] = acc;
    }
}

// ---------------- kernel E: reduce partials + context = S @ Wv + sumA * bv ----------------
__global__ __launch_bounds__(256) void ctx_tail_kernel(
    const float* __restrict__ Wv, const float* __restrict__ bv,
    float* __restrict__ out_ctx) {
    __shared__ float Ssh[VD];
    __shared__ float half1[DD];
    int b = blockIdx.x;
    int tid = threadIdx.x;
    float s = 0.f;
#pragma unroll
    for (int c = 0; c < 16; c++) s += g_Spart[c][b][tid];
    Ssh[tid] = s;
    __syncthreads();
    int d = tid & 127, hf = tid >> 7;
    float acc = 0.f;
    const float* wv = Wv + (size_t)hf * 128 * DD + d;
#pragma unroll 8
    for (int k = 0; k < 128; k++)
        acc += Ssh[hf * 128 + k] * wv[(size_t)k * DD];
    if (hf) half1[d] = acc;
    __syncthreads();
    if (hf == 0)
        out_ctx[b * DD + d] = acc + half1[d] + g_sumA[b] * bv[d];
}

// ---------------- launcher ----------------
extern "C" void kernel_launch(void* const* d_in, const int* in_sizes, int n_in,
                              void* d_out, int out_size) {
    (void)in_sizes; (void)n_in; (void)out_size;
    const float* query = (const float*)d_in[0];
    const float* value = (const float*)d_in[1];
    const float* prev  = (const float*)d_in[2];
    const float* Wq    = (const float*)d_in[3];
    const float* bq    = (const float*)d_in[4];
    const float* Wv    = (const float*)d_in[5];
    const float* bv    = (const float*)d_in[6];
    const float* av    = (const float*)d_in[7];
    const float* sbias = (const float*)d_in[8];

    float* out       = (float*)d_out;
    float* out_ctx   = out;                  // [32, 128]
    float* out_align = out + BB * DD;        // [32, 8192]

    const int SCORE_DYN = 2 * STAGE_BYTES + 1024;
    cudaFuncSetAttribute(score_kernel, cudaFuncAttributeMaxDynamicSharedMemorySize, SCORE_DYN);

    qproj_kernel<<<BB, 512>>>(query, Wq, bq);                 // launch 0
    wvt_kernel<<<dim3(VD / 32, DD / 32), dim3(32, 8)>>>(Wv);  // launch 1
    zero_kernel<<<1, 32>>>();                                 // launch 2
    score_kernel<<<dim3(TT / TILE_T, BB), 256, SCORE_DYN>>>(value, Wv, bv, av, sbias); // launch 3 -> ncu
    scan_kernel<<<BB, 512>>>(prev, out_align);
    ctx_reduce_kernel<<<dim3(16, BB), 512>>>(value, out_align);
    ctx_tail_kernel<<<BB, 256>>>(Wv, bv, out_ctx);
}